// round 1
// baseline (speedup 1.0000x reference)
#include <cuda_runtime.h>
#include <cstdint>

#define Bc 4
#define Tc 4096
#define Hc 2048
#define Dc 256
#define Nc 32768
#define Hq 512
#define MGP (Bc*Tc)          // 16384 rows for gate/prec GEMM
#define EPSC 1e-8f

// ---------------- device scratch (no allocations allowed) ----------------
__device__ float g_obs_mean[Tc * Dc];          // 4 MB
__device__ float g_oang[Tc * Dc];              // 4 MB
__device__ float g_part[8 * MGP];              // per-(ntile,row) partial logits
__device__ float g_binv[Nc];                   // 1/clip(||belief||,eps)
__device__ unsigned char g_active[Nc];
__device__ unsigned long long g_best[Tc];      // packed (enc(sim), ~idx)
__device__ float g_rad[Tc];                    // obs_radii
__device__ int g_fmt;                          // 0=int32 mask, 1=u8, 2=f32

// ---------------- helpers ----------------
__device__ __forceinline__ unsigned enc_f(float f) {
    unsigned u = __float_as_uint(f);
    return (u & 0x80000000u) ? ~u : (u | 0x80000000u);
}
__device__ __forceinline__ float dec_f(unsigned e) {
    unsigned u = (e & 0x80000000u) ? (e ^ 0x80000000u) : ~e;
    return __uint_as_float(u);
}
__device__ __forceinline__ float sigmoidf_(float x) { return 1.0f / (1.0f + expf(-x)); }
__device__ __forceinline__ float softplusf_(float x) {
    return fmaxf(x, 0.0f) + log1pf(expf(-fabsf(x)));
}

// ---------------- mask dtype detection (reads only N bytes: always in-bounds) ----
__global__ void detect_mask_kernel(const unsigned char* __restrict__ m, int nbytes) {
    __shared__ int weird, off4;
    if (threadIdx.x == 0) { weird = 0; off4 = 0; }
    __syncthreads();
    for (int i = threadIdx.x; i < nbytes; i += blockDim.x) {
        unsigned char c = m[i];
        if (c > 1) atomicOr(&weird, 1);
        if (c != 0 && (i & 3)) atomicOr(&off4, 1);
    }
    __syncthreads();
    if (threadIdx.x == 0) g_fmt = weird ? 2 : (off4 ? 1 : 0);
}

__global__ void convert_mask_kernel(const void* __restrict__ m) {
    int i = blockIdx.x * blockDim.x + threadIdx.x;
    if (i >= Nc) return;
    int fmt = g_fmt;
    unsigned char a;
    if (fmt == 0)      a = (((const int*)m)[i] != 0);
    else if (fmt == 1) a = (((const unsigned char*)m)[i] != 0);
    else               a = (((const float*)m)[i] != 0.0f);
    g_active[i] = a;
}

// ---------------- belief inverse radii: one warp per row ----------------
__global__ void binv_kernel(const float* __restrict__ beliefs) {
    int row = blockIdx.x * 8 + (threadIdx.x >> 5);
    int lane = threadIdx.x & 31;
    const float4* p = reinterpret_cast<const float4*>(beliefs + (size_t)row * Dc);
    float s = 0.0f;
    #pragma unroll
    for (int r = 0; r < 2; r++) {
        float4 v = p[lane + r * 32];
        s += v.x * v.x + v.y * v.y + v.z * v.z + v.w * v.w;
    }
    #pragma unroll
    for (int o = 16; o > 0; o >>= 1) s += __shfl_down_sync(0xffffffffu, s, o);
    if (lane == 0) g_binv[row] = 1.0f / fmaxf(sqrtf(s), EPSC);
}

// ---------------- gate/prec GEMM: [16384,2048] x [2048,128-tile] with fused
// relu + rank-1 second layer; writes per-(ntile,row) partial logits ----------
__global__ __launch_bounds__(256) void gemm_gp_kernel(
    const float* __restrict__ A,
    const float* __restrict__ Wg1, const float* __restrict__ Wp1,
    const float* __restrict__ bg1, const float* __restrict__ bp1,
    const float* __restrict__ Wg2, const float* __restrict__ Wp2)
{
    const int K = Hc;
    const int m0 = blockIdx.x * 128;
    const int by = blockIdx.y;                  // 0..7 ; 0-3 gate, 4-7 prec
    const float* W1 = (by < 4) ? Wg1 : Wp1;
    const float* W2 = (by < 4) ? Wg2 : Wp2;
    const float* B1 = (by < 4) ? bg1 : bp1;
    const int nbase = (by & 3) * 128;

    __shared__ float As[8][128];
    __shared__ float Bs[8][128];
    __shared__ float w2s[128];
    __shared__ float b1s[128];
    __shared__ float red[128][17];

    int tid = threadIdx.x;
    if (tid < 128) { w2s[tid] = W2[nbase + tid]; b1s[tid] = B1[nbase + tid]; }

    int lrow = tid >> 1;
    int lcol = (tid & 1) * 4;
    int ty = tid >> 4, tx = tid & 15;

    float acc[8][8];
    #pragma unroll
    for (int i = 0; i < 8; i++)
        #pragma unroll
        for (int j = 0; j < 8; j++) acc[i][j] = 0.0f;

    for (int k0 = 0; k0 < K; k0 += 8) {
        float4 av = *reinterpret_cast<const float4*>(A + (size_t)(m0 + lrow) * K + k0 + lcol);
        float4 bv = *reinterpret_cast<const float4*>(W1 + (size_t)(nbase + lrow) * K + k0 + lcol);
        __syncthreads();
        As[lcol + 0][lrow] = av.x; As[lcol + 1][lrow] = av.y;
        As[lcol + 2][lrow] = av.z; As[lcol + 3][lrow] = av.w;
        Bs[lcol + 0][lrow] = bv.x; Bs[lcol + 1][lrow] = bv.y;
        Bs[lcol + 2][lrow] = bv.z; Bs[lcol + 3][lrow] = bv.w;
        __syncthreads();
        #pragma unroll
        for (int kk = 0; kk < 8; kk++) {
            float4 a0 = *reinterpret_cast<const float4*>(&As[kk][ty * 8]);
            float4 a1 = *reinterpret_cast<const float4*>(&As[kk][ty * 8 + 4]);
            float4 b0 = *reinterpret_cast<const float4*>(&Bs[kk][tx * 8]);
            float4 b1 = *reinterpret_cast<const float4*>(&Bs[kk][tx * 8 + 4]);
            float a[8] = {a0.x,a0.y,a0.z,a0.w,a1.x,a1.y,a1.z,a1.w};
            float b[8] = {b0.x,b0.y,b0.z,b0.w,b1.x,b1.y,b1.z,b1.w};
            #pragma unroll
            for (int i = 0; i < 8; i++)
                #pragma unroll
                for (int j = 0; j < 8; j++) acc[i][j] += a[i] * b[j];
        }
    }

    // fused second layer: relu(acc + b1) dotted with w2, reduced over n-tile
    float s[8];
    #pragma unroll
    for (int i = 0; i < 8; i++) {
        float t = 0.0f;
        #pragma unroll
        for (int j = 0; j < 8; j++) {
            float c = fmaxf(acc[i][j] + b1s[tx * 8 + j], 0.0f);
            t += c * w2s[tx * 8 + j];
        }
        s[i] = t;
    }
    #pragma unroll
    for (int i = 0; i < 8; i++) red[ty * 8 + i][tx] = s[i];
    __syncthreads();
    if (tid < 128) {
        float tot = 0.0f;
        #pragma unroll
        for (int x = 0; x < 16; x++) tot += red[tid][x];
        g_part[by * MGP + m0 + tid] = tot;
    }
}

// ---------------- obs GEMM: mean-over-B fused into A loads -----------------
__global__ __launch_bounds__(256) void gemm_obs_kernel(
    const float* __restrict__ hidden, const float* __restrict__ Wobs)
{
    const int K = Hc;
    const int m0 = blockIdx.x * 128;
    const int nbase = blockIdx.y * 128;
    const size_t bstride = (size_t)Tc * Hc;

    __shared__ float As[8][128];
    __shared__ float Bs[8][128];

    int tid = threadIdx.x;
    int lrow = tid >> 1;
    int lcol = (tid & 1) * 4;
    int ty = tid >> 4, tx = tid & 15;

    float acc[8][8];
    #pragma unroll
    for (int i = 0; i < 8; i++)
        #pragma unroll
        for (int j = 0; j < 8; j++) acc[i][j] = 0.0f;

    for (int k0 = 0; k0 < K; k0 += 8) {
        float4 av = make_float4(0,0,0,0);
        size_t base = (size_t)(m0 + lrow) * K + k0 + lcol;
        #pragma unroll
        for (int b = 0; b < Bc; b++) {
            float4 v = *reinterpret_cast<const float4*>(hidden + b * bstride + base);
            av.x += v.x; av.y += v.y; av.z += v.z; av.w += v.w;
        }
        av.x *= 0.25f; av.y *= 0.25f; av.z *= 0.25f; av.w *= 0.25f;
        float4 bv = *reinterpret_cast<const float4*>(Wobs + (size_t)(nbase + lrow) * K + k0 + lcol);
        __syncthreads();
        As[lcol + 0][lrow] = av.x; As[lcol + 1][lrow] = av.y;
        As[lcol + 2][lrow] = av.z; As[lcol + 3][lrow] = av.w;
        Bs[lcol + 0][lrow] = bv.x; Bs[lcol + 1][lrow] = bv.y;
        Bs[lcol + 2][lrow] = bv.z; Bs[lcol + 3][lrow] = bv.w;
        __syncthreads();
        #pragma unroll
        for (int kk = 0; kk < 8; kk++) {
            float4 a0 = *reinterpret_cast<const float4*>(&As[kk][ty * 8]);
            float4 a1 = *reinterpret_cast<const float4*>(&As[kk][ty * 8 + 4]);
            float4 b0 = *reinterpret_cast<const float4*>(&Bs[kk][tx * 8]);
            float4 b1 = *reinterpret_cast<const float4*>(&Bs[kk][tx * 8 + 4]);
            float a[8] = {a0.x,a0.y,a0.z,a0.w,a1.x,a1.y,a1.z,a1.w};
            float b[8] = {b0.x,b0.y,b0.z,b0.w,b1.x,b1.y,b1.z,b1.w};
            #pragma unroll
            for (int i = 0; i < 8; i++)
                #pragma unroll
                for (int j = 0; j < 8; j++) acc[i][j] += a[i] * b[j];
        }
    }
    #pragma unroll
    for (int i = 0; i < 8; i++) {
        float* dst = &g_obs_mean[(size_t)(m0 + ty * 8 + i) * Dc + nbase + tx * 8];
        *reinterpret_cast<float4*>(dst)     = make_float4(acc[i][0], acc[i][1], acc[i][2], acc[i][3]);
        *reinterpret_cast<float4*>(dst + 4) = make_float4(acc[i][4], acc[i][5], acc[i][6], acc[i][7]);
    }
}

// ---------------- finalize1: per-t normalize, gate/prec combine -------------
__global__ __launch_bounds__(256) void finalize1_kernel(
    const float* __restrict__ bg2, const float* __restrict__ bp2,
    float* __restrict__ out_obs, float* __restrict__ out_meaning, int write_extra)
{
    __shared__ float sred[256];
    __shared__ float s_pm, s_inv, s_rinv;
    int t = blockIdx.x;
    int d = threadIdx.x;
    float v = g_obs_mean[(size_t)t * Dc + d];

    sred[d] = v * v;
    __syncthreads();
    for (int s = 128; s > 0; s >>= 1) {
        if (d < s) sred[d] += sred[d + s];
        __syncthreads();
    }
    if (d == 0) {
        float pm = 0.0f;
        float bg2v = bg2[0], bp2v = bp2[0];
        #pragma unroll
        for (int b = 0; b < Bc; b++) {
            int row = b * Tc + t;
            float gl = bg2v, pl = bp2v;
            #pragma unroll
            for (int jt = 0; jt < 4; jt++) gl += g_part[jt * MGP + row];
            #pragma unroll
            for (int jt = 4; jt < 8; jt++) pl += g_part[jt * MGP + row];
            pm += sigmoidf_(gl) * softplusf_(pl);
        }
        pm *= 0.25f;
        float nrm = sqrtf(sred[0]);
        s_pm = pm;
        s_inv = 1.0f / fmaxf(nrm, EPSC);
    }
    __syncthreads();
    float ob = v * s_inv * s_pm;
    out_obs[(size_t)t * Dc + d] = ob;

    __syncthreads();
    sred[d] = ob * ob;
    __syncthreads();
    for (int s = 128; s > 0; s >>= 1) {
        if (d < s) sred[d] += sred[d + s];
        __syncthreads();
    }
    if (d == 0) {
        float r = sqrtf(sred[0]);
        g_rad[t] = r;
        s_rinv = 1.0f / fmaxf(r, EPSC);
        if (write_extra) out_meaning[t] = (r > 0.05f) ? 1.0f : 0.0f;
    }
    __syncthreads();
    g_oang[(size_t)t * Dc + d] = ob * s_rinv;
}

__global__ void init_best_kernel() {
    int i = blockIdx.x * blockDim.x + threadIdx.x;
    if (i < Tc) g_best[i] = 0ULL;
}

// ---------------- sims GEMM with masked max/argmax epilogue -----------------
__global__ __launch_bounds__(256) void sims_kernel(const float* __restrict__ beliefs)
{
    const int K = Dc;
    const int m0 = blockIdx.x * 128;
    const int n0 = blockIdx.y * 128;

    __shared__ float As[8][128];
    __shared__ float Bs[8][128];
    __shared__ float binv_s[128];
    __shared__ unsigned char act_s[128];
    __shared__ unsigned long long redu[128][16];

    int tid = threadIdx.x;
    if (tid < 128) { binv_s[tid] = g_binv[n0 + tid]; act_s[tid] = g_active[n0 + tid]; }

    int lrow = tid >> 1;
    int lcol = (tid & 1) * 4;
    int ty = tid >> 4, tx = tid & 15;

    float acc[8][8];
    #pragma unroll
    for (int i = 0; i < 8; i++)
        #pragma unroll
        for (int j = 0; j < 8; j++) acc[i][j] = 0.0f;

    for (int k0 = 0; k0 < K; k0 += 8) {
        float4 av = *reinterpret_cast<const float4*>(g_oang + (size_t)(m0 + lrow) * K + k0 + lcol);
        float4 bv = *reinterpret_cast<const float4*>(beliefs + (size_t)(n0 + lrow) * K + k0 + lcol);
        __syncthreads();
        As[lcol + 0][lrow] = av.x; As[lcol + 1][lrow] = av.y;
        As[lcol + 2][lrow] = av.z; As[lcol + 3][lrow] = av.w;
        Bs[lcol + 0][lrow] = bv.x; Bs[lcol + 1][lrow] = bv.y;
        Bs[lcol + 2][lrow] = bv.z; Bs[lcol + 3][lrow] = bv.w;
        __syncthreads();
        #pragma unroll
        for (int kk = 0; kk < 8; kk++) {
            float4 a0 = *reinterpret_cast<const float4*>(&As[kk][ty * 8]);
            float4 a1 = *reinterpret_cast<const float4*>(&As[kk][ty * 8 + 4]);
            float4 b0 = *reinterpret_cast<const float4*>(&Bs[kk][tx * 8]);
            float4 b1 = *reinterpret_cast<const float4*>(&Bs[kk][tx * 8 + 4]);
            float a[8] = {a0.x,a0.y,a0.z,a0.w,a1.x,a1.y,a1.z,a1.w};
            float b[8] = {b0.x,b0.y,b0.z,b0.w,b1.x,b1.y,b1.z,b1.w};
            #pragma unroll
            for (int i = 0; i < 8; i++)
                #pragma unroll
                for (int j = 0; j < 8; j++) acc[i][j] += a[i] * b[j];
        }
    }

    unsigned long long best[8];
    #pragma unroll
    for (int i = 0; i < 8; i++) best[i] = 0ULL;
    #pragma unroll
    for (int j = 0; j < 8; j++) {
        int ln = tx * 8 + j;
        if (act_s[ln]) {
            float bi = binv_s[ln];
            unsigned key2 = 0xFFFFFFFFu - (unsigned)(n0 + ln);
            #pragma unroll
            for (int i = 0; i < 8; i++) {
                float sim = acc[i][j] * bi;
                unsigned long long p = ((unsigned long long)enc_f(sim) << 32) | key2;
                if (p > best[i]) best[i] = p;
            }
        }
    }
    #pragma unroll
    for (int i = 0; i < 8; i++) redu[ty * 8 + i][tx] = best[i];
    __syncthreads();
    if (tid < 128) {
        unsigned long long m = 0ULL;
        #pragma unroll
        for (int x = 0; x < 16; x++) { unsigned long long v = redu[tid][x]; if (v > m) m = v; }
        if (m != 0ULL) atomicMax(&g_best[m0 + tid], m);
    }
}

// ---------------- finalize2: match decision -----------------
__global__ void finalize2_kernel(float* __restrict__ out_sims, float* __restrict__ out_slots)
{
    int t = blockIdx.x * blockDim.x + threadIdx.x;
    if (t >= Tc) return;
    unsigned long long b = g_best[t];
    float sim = 0.0f;
    int idx = -1;
    bool has = (b != 0ULL);
    if (has) {
        sim = dec_f((unsigned)(b >> 32));
        idx = (int)(0xFFFFFFFFu - (unsigned)(b & 0xFFFFFFFFu));
    }
    bool matched = has && (g_rad[t] > 0.05f) && (sim > 0.5f);
    out_sims[t]  = matched ? sim : 0.0f;
    out_slots[t] = matched ? (float)idx : -1.0f;
}

// ---------------- launcher ----------------
extern "C" void kernel_launch(void* const* d_in, const int* in_sizes, int n_in,
                              void* d_out, int out_size)
{
    const float* hidden  = (const float*)d_in[0];
    const float* beliefs = (const float*)d_in[1];
    const void*  maskp   = d_in[2];
    const float* W_obs   = (const float*)d_in[3];
    const float* W_g1    = (const float*)d_in[4];
    const float* b_g1    = (const float*)d_in[5];
    const float* W_g2    = (const float*)d_in[6];
    const float* b_g2    = (const float*)d_in[7];
    const float* W_p1    = (const float*)d_in[8];
    const float* b_p1    = (const float*)d_in[9];
    const float* W_p2    = (const float*)d_in[10];
    const float* b_p2    = (const float*)d_in[11];
    float* out = (float*)d_out;

    const size_t base = (size_t)Tc * Dc;
    const int write_extra = (out_size >= (int)(base + 3 * Tc)) ? 1 : 0;
    float* out_obs     = out;
    float* out_sims    = out + base;
    float* out_slots   = out + base + Tc;
    float* out_meaning = out + base + 2 * Tc;

    detect_mask_kernel<<<1, 256>>>((const unsigned char*)maskp, Nc);
    convert_mask_kernel<<<Nc / 256, 256>>>(maskp);
    binv_kernel<<<Nc / 8, 256>>>(beliefs);

    gemm_gp_kernel<<<dim3(MGP / 128, 8), 256>>>(hidden, W_g1, W_p1, b_g1, b_p1, W_g2, W_p2);
    gemm_obs_kernel<<<dim3(Tc / 128, Dc / 128), 256>>>(hidden, W_obs);
    finalize1_kernel<<<Tc, 256>>>(b_g2, b_p2, out_obs, out_meaning, write_extra);

    init_best_kernel<<<Tc / 256, 256>>>();
    sims_kernel<<<dim3(Tc / 128, Nc / 128), 256>>>(beliefs);
    if (write_extra) {
        finalize2_kernel<<<Tc / 256, 256>>>(out_sims, out_slots);
    }
}

// round 3
// speedup vs baseline: 2.2370x; 2.2370x over previous
#include <cuda_runtime.h>
#include <cuda_bf16.h>
#include <cstdint>

#define Bc 4
#define Tc 4096
#define Hc 2048
#define Dc 256
#define Nc 32768
#define MGP (Bc*Tc)
#define EPSC 1e-8f

// ---------------- device scratch ----------------
__device__ __nv_bfloat16 g_Ahi[(size_t)MGP * Hc];
__device__ __nv_bfloat16 g_Alo[(size_t)MGP * Hc];
__device__ __nv_bfloat16 g_Hmhi[(size_t)Tc * Hc];
__device__ __nv_bfloat16 g_Hmlo[(size_t)Tc * Hc];
__device__ __nv_bfloat16 g_Wchi[(size_t)1024 * Hc];
__device__ __nv_bfloat16 g_Wclo[(size_t)1024 * Hc];
__device__ __nv_bfloat16 g_Wohi[(size_t)Dc * Hc];
__device__ __nv_bfloat16 g_Wolo[(size_t)Dc * Hc];
__device__ __nv_bfloat16 g_Bb[(size_t)Nc * Dc];
__device__ __nv_bfloat16 g_oangb[(size_t)Tc * Dc];
__device__ float g_bc1[1024];
__device__ float g_wc2[1024];
__device__ float g_obs_mean[(size_t)Tc * Dc];
__device__ float g_part[8 * MGP];
__device__ float g_binv[Nc];
__device__ unsigned char g_active[Nc];
__device__ unsigned long long g_best[Tc];
__device__ float g_rad[Tc];
__device__ int g_fmt;

// ---------------- helpers ----------------
__device__ __forceinline__ uint32_t smem_u32(const void* p) {
    uint32_t a;
    asm("{ .reg .u64 t; cvta.to.shared.u64 t, %1; cvt.u32.u64 %0, t; }" : "=r"(a) : "l"(p));
    return a;
}
#define LDSM4(R0, R1, R2, R3, A) \
    asm volatile("ldmatrix.sync.aligned.m8n8.x4.shared.b16 {%0,%1,%2,%3}, [%4];" \
        : "=r"(R0), "=r"(R1), "=r"(R2), "=r"(R3) : "r"(A))
#define MMA_BF16(D, A, B) \
    asm volatile("mma.sync.aligned.m16n8k16.row.col.f32.bf16.bf16.f32 " \
        "{%0,%1,%2,%3}, {%4,%5,%6,%7}, {%8,%9}, {%0,%1,%2,%3};" \
        : "+f"((D)[0]), "+f"((D)[1]), "+f"((D)[2]), "+f"((D)[3]) \
        : "r"((A)[0]), "r"((A)[1]), "r"((A)[2]), "r"((A)[3]), "r"((B)[0]), "r"((B)[1]))

__device__ __forceinline__ unsigned enc_f(float f) {
    unsigned u = __float_as_uint(f);
    return (u & 0x80000000u) ? ~u : (u | 0x80000000u);
}
__device__ __forceinline__ float dec_f(unsigned e) {
    unsigned u = (e & 0x80000000u) ? (e ^ 0x80000000u) : ~e;
    return __uint_as_float(u);
}
__device__ __forceinline__ float sigmoidf_(float x) { return 1.0f / (1.0f + expf(-x)); }
__device__ __forceinline__ float softplusf_(float x) {
    return fmaxf(x, 0.0f) + log1pf(expf(-fabsf(x)));
}
__device__ __forceinline__ void split_store(__nv_bfloat16* hi, __nv_bfloat16* lo, float4 v) {
    __nv_bfloat16 h0 = __float2bfloat16_rn(v.x);
    __nv_bfloat16 h1 = __float2bfloat16_rn(v.y);
    __nv_bfloat16 h2 = __float2bfloat16_rn(v.z);
    __nv_bfloat16 h3 = __float2bfloat16_rn(v.w);
    __nv_bfloat16 l0 = __float2bfloat16_rn(v.x - __bfloat162float(h0));
    __nv_bfloat16 l1 = __float2bfloat16_rn(v.y - __bfloat162float(h1));
    __nv_bfloat16 l2 = __float2bfloat16_rn(v.z - __bfloat162float(h2));
    __nv_bfloat16 l3 = __float2bfloat16_rn(v.w - __bfloat162float(h3));
    ((__nv_bfloat162*)hi)[0] = __nv_bfloat162(h0, h1);
    ((__nv_bfloat162*)hi)[1] = __nv_bfloat162(h2, h3);
    ((__nv_bfloat162*)lo)[0] = __nv_bfloat162(l0, l1);
    ((__nv_bfloat162*)lo)[1] = __nv_bfloat162(l2, l3);
}

// ---------------- prep kernels ----------------
__global__ void prep_hidden_kernel(const float* __restrict__ hidden) {
    int idx = blockIdx.x * blockDim.x + threadIdx.x;
    int t = idx >> 9, h = (idx & 511) * 4;
    float4 acc = make_float4(0, 0, 0, 0);
    #pragma unroll
    for (int b = 0; b < Bc; b++) {
        size_t row = (size_t)(b * Tc + t);
        float4 v = *(const float4*)(hidden + row * Hc + h);
        split_store(g_Ahi + row * Hc + h, g_Alo + row * Hc + h, v);
        acc.x += v.x; acc.y += v.y; acc.z += v.z; acc.w += v.w;
    }
    acc.x *= 0.25f; acc.y *= 0.25f; acc.z *= 0.25f; acc.w *= 0.25f;
    split_store(g_Hmhi + (size_t)t * Hc + h, g_Hmlo + (size_t)t * Hc + h, acc);
}

__global__ void prep_weights_kernel(const float* __restrict__ Wg1, const float* __restrict__ Wp1,
                                    const float* __restrict__ Wobs) {
    int idx = blockIdx.x * blockDim.x + threadIdx.x;
    int row = idx >> 9, h = (idx & 511) * 4;
    if (row < 1024) {
        const float* src = (row < 512) ? (Wg1 + (size_t)row * Hc) : (Wp1 + (size_t)(row - 512) * Hc);
        float4 v = *(const float4*)(src + h);
        split_store(g_Wchi + (size_t)row * Hc + h, g_Wclo + (size_t)row * Hc + h, v);
    } else {
        int r2 = row - 1024;
        float4 v = *(const float4*)(Wobs + (size_t)r2 * Hc + h);
        split_store(g_Wohi + (size_t)r2 * Hc + h, g_Wolo + (size_t)r2 * Hc + h, v);
    }
}

__global__ void prep_small_kernel(const float* __restrict__ bg1, const float* __restrict__ bp1,
                                  const float* __restrict__ Wg2, const float* __restrict__ Wp2) {
    int i = blockIdx.x * blockDim.x + threadIdx.x;
    if (i < 1024) {
        g_bc1[i] = (i < 512) ? bg1[i] : bp1[i - 512];
        g_wc2[i] = (i < 512) ? Wg2[i] : Wp2[i - 512];
    }
}

__global__ void prep_beliefs_kernel(const float* __restrict__ beliefs) {
    int idx = blockIdx.x * blockDim.x + threadIdx.x;
    size_t e = (size_t)idx * 4;
    float4 v = *(const float4*)(beliefs + e);
    ((__nv_bfloat162*)(g_Bb + e))[0] = __nv_bfloat162(__float2bfloat16_rn(v.x), __float2bfloat16_rn(v.y));
    ((__nv_bfloat162*)(g_Bb + e))[1] = __nv_bfloat162(__float2bfloat16_rn(v.z), __float2bfloat16_rn(v.w));
}

__global__ void detect_mask_kernel(const unsigned char* __restrict__ m, int nbytes) {
    __shared__ int weird, off4;
    if (threadIdx.x == 0) { weird = 0; off4 = 0; }
    __syncthreads();
    for (int i = threadIdx.x; i < nbytes; i += blockDim.x) {
        unsigned char c = m[i];
        if (c > 1) atomicOr(&weird, 1);
        if (c != 0 && (i & 3)) atomicOr(&off4, 1);
    }
    __syncthreads();
    if (threadIdx.x == 0) g_fmt = weird ? 2 : (off4 ? 1 : 0);
}
__global__ void convert_mask_kernel(const void* __restrict__ m) {
    int i = blockIdx.x * blockDim.x + threadIdx.x;
    if (i >= Nc) return;
    int fmt = g_fmt;
    unsigned char a;
    if (fmt == 0)      a = (((const int*)m)[i] != 0);
    else if (fmt == 1) a = (((const unsigned char*)m)[i] != 0);
    else               a = (((const float*)m)[i] != 0.0f);
    g_active[i] = a;
}
__global__ void binv_kernel(const float* __restrict__ beliefs) {
    int row = blockIdx.x * 8 + (threadIdx.x >> 5);
    int lane = threadIdx.x & 31;
    const float4* p = reinterpret_cast<const float4*>(beliefs + (size_t)row * Dc);
    float s = 0.0f;
    #pragma unroll
    for (int r = 0; r < 2; r++) {
        float4 v = p[lane + r * 32];
        s += v.x * v.x + v.y * v.y + v.z * v.z + v.w * v.w;
    }
    #pragma unroll
    for (int o = 16; o > 0; o >>= 1) s += __shfl_down_sync(0xffffffffu, s, o);
    if (lane == 0) g_binv[row] = 1.0f / fmaxf(sqrtf(s), EPSC);
}

// ============ gate/prec GEMM: mma.sync split-bf16, 3 terms, K=2048 ============
// block 128x128, 8 warps, warp tile 32x64, K-chunk 32, smem rows padded to 80B.
__global__ __launch_bounds__(256, 1) void gp_mma_kernel() {
    __shared__ __align__(16) char sAh[128 * 80];
    __shared__ __align__(16) char sAl[128 * 80];
    __shared__ __align__(16) char sBh[128 * 80];
    __shared__ __align__(16) char sBl[128 * 80];
    __shared__ float s_b1[128], s_w2[128], s_red[128];

    const int tid = threadIdx.x, lane = tid & 31, wid = tid >> 5;
    const int bx = blockIdx.x;            // n-tile 0..7
    const int m0 = blockIdx.y * 128;
    const int nbase = bx * 128;
    const int warp_m = (wid >> 1) * 32;
    const int warp_n = (wid & 1) * 64;

    if (tid < 128) {
        s_b1[tid] = g_bc1[nbase + tid];
        s_w2[tid] = g_wc2[nbase + tid];
        s_red[tid] = 0.0f;
    }

    const int r = tid >> 1, seg = tid & 1;
    const __nv_bfloat16* pAh = g_Ahi + (size_t)(m0 + r) * Hc + seg * 16;
    const __nv_bfloat16* pAl = g_Alo + (size_t)(m0 + r) * Hc + seg * 16;
    const __nv_bfloat16* pBh = g_Wchi + (size_t)(nbase + r) * Hc + seg * 16;
    const __nv_bfloat16* pBl = g_Wclo + (size_t)(nbase + r) * Hc + seg * 16;
    char* dAh = sAh + r * 80 + seg * 32;
    char* dAl = sAl + r * 80 + seg * 32;
    char* dBh = sBh + r * 80 + seg * 32;
    char* dBl = sBl + r * 80 + seg * 32;

    const uint32_t uAh = smem_u32(sAh), uAl = smem_u32(sAl);
    const uint32_t uBh = smem_u32(sBh), uBl = smem_u32(sBl);
    const uint32_t offA = (uint32_t)(warp_m + (lane & 15)) * 80 + (uint32_t)(lane >> 4) * 16;
    const uint32_t offB = (uint32_t)(warp_n + ((lane >> 4) << 3) + (lane & 7)) * 80
                        + (uint32_t)((lane >> 3) & 1) * 16;

    float acc[2][8][4];
    #pragma unroll
    for (int i = 0; i < 2; i++)
        #pragma unroll
        for (int j = 0; j < 8; j++)
            #pragma unroll
            for (int k = 0; k < 4; k++) acc[i][j][k] = 0.0f;

    for (int c = 0; c < Hc / 32; c++) {
        const int k0 = c * 32;
        __syncthreads();
        *(uint4*)dAh        = *(const uint4*)(pAh + k0);
        *(uint4*)(dAh + 16) = *(const uint4*)(pAh + k0 + 8);
        *(uint4*)dAl        = *(const uint4*)(pAl + k0);
        *(uint4*)(dAl + 16) = *(const uint4*)(pAl + k0 + 8);
        *(uint4*)dBh        = *(const uint4*)(pBh + k0);
        *(uint4*)(dBh + 16) = *(const uint4*)(pBh + k0 + 8);
        *(uint4*)dBl        = *(const uint4*)(pBl + k0);
        *(uint4*)(dBl + 16) = *(const uint4*)(pBl + k0 + 8);
        __syncthreads();
        #pragma unroll
        for (int ks = 0; ks < 2; ks++) {
            uint32_t ah[2][4], al[2][4];
            LDSM4(ah[0][0], ah[0][1], ah[0][2], ah[0][3], uAh + offA + ks * 32);
            LDSM4(ah[1][0], ah[1][1], ah[1][2], ah[1][3], uAh + offA + 1280 + ks * 32);
            LDSM4(al[0][0], al[0][1], al[0][2], al[0][3], uAl + offA + ks * 32);
            LDSM4(al[1][0], al[1][1], al[1][2], al[1][3], uAl + offA + 1280 + ks * 32);
            uint32_t bh[8][2], bl[8][2];
            #pragma unroll
            for (int jp = 0; jp < 4; jp++) {
                LDSM4(bh[2*jp][0], bh[2*jp][1], bh[2*jp+1][0], bh[2*jp+1][1],
                      uBh + offB + (uint32_t)jp * 1280 + ks * 32);
                LDSM4(bl[2*jp][0], bl[2*jp][1], bl[2*jp+1][0], bl[2*jp+1][1],
                      uBl + offB + (uint32_t)jp * 1280 + ks * 32);
            }
            #pragma unroll
            for (int mt = 0; mt < 2; mt++)
                #pragma unroll
                for (int nj = 0; nj < 8; nj++) {
                    MMA_BF16(acc[mt][nj], ah[mt], bh[nj]);
                    MMA_BF16(acc[mt][nj], ah[mt], bl[nj]);
                    MMA_BF16(acc[mt][nj], al[mt], bh[nj]);
                }
        }
    }

    // fused relu + rank-1 epilogue
    __syncthreads();
    const int qr = lane >> 2;
    const int qc = (lane & 3) * 2;
    #pragma unroll
    for (int mt = 0; mt < 2; mt++) {
        float p0 = 0.0f, p1 = 0.0f;
        #pragma unroll
        for (int nj = 0; nj < 8; nj++) {
            int col = warp_n + nj * 8 + qc;
            p0 += fmaxf(acc[mt][nj][0] + s_b1[col], 0.0f) * s_w2[col]
                + fmaxf(acc[mt][nj][1] + s_b1[col + 1], 0.0f) * s_w2[col + 1];
            p1 += fmaxf(acc[mt][nj][2] + s_b1[col], 0.0f) * s_w2[col]
                + fmaxf(acc[mt][nj][3] + s_b1[col + 1], 0.0f) * s_w2[col + 1];
        }
        p0 += __shfl_xor_sync(0xffffffffu, p0, 1);
        p0 += __shfl_xor_sync(0xffffffffu, p0, 2);
        p1 += __shfl_xor_sync(0xffffffffu, p1, 1);
        p1 += __shfl_xor_sync(0xffffffffu, p1, 2);
        if ((lane & 3) == 0) {
            atomicAdd(&s_red[warp_m + mt * 16 + qr], p0);
            atomicAdd(&s_red[warp_m + mt * 16 + 8 + qr], p1);
        }
    }
    __syncthreads();
    if (tid < 128) g_part[bx * MGP + m0 + tid] = s_red[tid];
}

// ============ obs GEMM: mma.sync split-bf16 on batch-mean hidden ============
__global__ __launch_bounds__(256, 1) void obs_mma_kernel() {
    __shared__ __align__(16) char sAh[128 * 80];
    __shared__ __align__(16) char sAl[128 * 80];
    __shared__ __align__(16) char sBh[128 * 80];
    __shared__ __align__(16) char sBl[128 * 80];

    const int tid = threadIdx.x, lane = tid & 31, wid = tid >> 5;
    const int m0 = blockIdx.y * 128;
    const int nbase = blockIdx.x * 128;
    const int warp_m = (wid >> 1) * 32;
    const int warp_n = (wid & 1) * 64;

    const int r = tid >> 1, seg = tid & 1;
    const __nv_bfloat16* pAh = g_Hmhi + (size_t)(m0 + r) * Hc + seg * 16;
    const __nv_bfloat16* pAl = g_Hmlo + (size_t)(m0 + r) * Hc + seg * 16;
    const __nv_bfloat16* pBh = g_Wohi + (size_t)(nbase + r) * Hc + seg * 16;
    const __nv_bfloat16* pBl = g_Wolo + (size_t)(nbase + r) * Hc + seg * 16;
    char* dAh = sAh + r * 80 + seg * 32;
    char* dAl = sAl + r * 80 + seg * 32;
    char* dBh = sBh + r * 80 + seg * 32;
    char* dBl = sBl + r * 80 + seg * 32;

    const uint32_t uAh = smem_u32(sAh), uAl = smem_u32(sAl);
    const uint32_t uBh = smem_u32(sBh), uBl = smem_u32(sBl);
    const uint32_t offA = (uint32_t)(warp_m + (lane & 15)) * 80 + (uint32_t)(lane >> 4) * 16;
    const uint32_t offB = (uint32_t)(warp_n + ((lane >> 4) << 3) + (lane & 7)) * 80
                        + (uint32_t)((lane >> 3) & 1) * 16;

    float acc[2][8][4];
    #pragma unroll
    for (int i = 0; i < 2; i++)
        #pragma unroll
        for (int j = 0; j < 8; j++)
            #pragma unroll
            for (int k = 0; k < 4; k++) acc[i][j][k] = 0.0f;

    for (int c = 0; c < Hc / 32; c++) {
        const int k0 = c * 32;
        __syncthreads();
        *(uint4*)dAh        = *(const uint4*)(pAh + k0);
        *(uint4*)(dAh + 16) = *(const uint4*)(pAh + k0 + 8);
        *(uint4*)dAl        = *(const uint4*)(pAl + k0);
        *(uint4*)(dAl + 16) = *(const uint4*)(pAl + k0 + 8);
        *(uint4*)dBh        = *(const uint4*)(pBh + k0);
        *(uint4*)(dBh + 16) = *(const uint4*)(pBh + k0 + 8);
        *(uint4*)dBl        = *(const uint4*)(pBl + k0);
        *(uint4*)(dBl + 16) = *(const uint4*)(pBl + k0 + 8);
        __syncthreads();
        #pragma unroll
        for (int ks = 0; ks < 2; ks++) {
            uint32_t ah[2][4], al[2][4];
            LDSM4(ah[0][0], ah[0][1], ah[0][2], ah[0][3], uAh + offA + ks * 32);
            LDSM4(ah[1][0], ah[1][1], ah[1][2], ah[1][3], uAh + offA + 1280 + ks * 32);
            LDSM4(al[0][0], al[0][1], al[0][2], al[0][3], uAl + offA + ks * 32);
            LDSM4(al[1][0], al[1][1], al[1][2], al[1][3], uAl + offA + 1280 + ks * 32);
            uint32_t bh[8][2], bl[8][2];
            #pragma unroll
            for (int jp = 0; jp < 4; jp++) {
                LDSM4(bh[2*jp][0], bh[2*jp][1], bh[2*jp+1][0], bh[2*jp+1][1],
                      uBh + offB + (uint32_t)jp * 1280 + ks * 32);
                LDSM4(bl[2*jp][0], bl[2*jp][1], bl[2*jp+1][0], bl[2*jp+1][1],
                      uBl + offB + (uint32_t)jp * 1280 + ks * 32);
            }
            #pragma unroll
            for (int mt = 0; mt < 2; mt++)
                #pragma unroll
                for (int nj = 0; nj < 8; nj++) {
                    MMA_BF16(acc[mt][nj], ah[mt], bh[nj]);
                    MMA_BF16(acc[mt][nj], ah[mt], bl[nj]);
                    MMA_BF16(acc[mt][nj], al[mt], bh[nj]);
                }
        }
    }

    const int qr = lane >> 2;
    const int qc = (lane & 3) * 2;
    #pragma unroll
    for (int mt = 0; mt < 2; mt++)
        #pragma unroll
        for (int nj = 0; nj < 8; nj++) {
            int row = m0 + warp_m + mt * 16 + qr;
            int col = nbase + warp_n + nj * 8 + qc;
            *(float2*)(g_obs_mean + (size_t)row * Dc + col) = make_float2(acc[mt][nj][0], acc[mt][nj][1]);
            *(float2*)(g_obs_mean + (size_t)(row + 8) * Dc + col) = make_float2(acc[mt][nj][2], acc[mt][nj][3]);
        }
}

// ============ sims GEMM: bf16 mma.sync + masked max/argmax epilogue ============
__global__ __launch_bounds__(256, 1) void sims_mma_kernel() {
    __shared__ __align__(16) char sA[128 * 80];
    __shared__ __align__(16) char sB[128 * 80];
    __shared__ float s_binv[128];
    __shared__ unsigned char s_act[128];

    const int tid = threadIdx.x, lane = tid & 31, wid = tid >> 5;
    const int n0 = blockIdx.x * 128;
    const int m0 = blockIdx.y * 128;
    const int warp_m = (wid >> 1) * 32;
    const int warp_n = (wid & 1) * 64;

    if (tid < 128) { s_binv[tid] = g_binv[n0 + tid]; s_act[tid] = g_active[n0 + tid]; }

    const int r = tid >> 1, seg = tid & 1;
    const __nv_bfloat16* pA = g_oangb + (size_t)(m0 + r) * Dc + seg * 16;
    const __nv_bfloat16* pB = g_Bb + (size_t)(n0 + r) * Dc + seg * 16;
    char* dA = sA + r * 80 + seg * 32;
    char* dB = sB + r * 80 + seg * 32;

    const uint32_t uA = smem_u32(sA), uB = smem_u32(sB);
    const uint32_t offA = (uint32_t)(warp_m + (lane & 15)) * 80 + (uint32_t)(lane >> 4) * 16;
    const uint32_t offB = (uint32_t)(warp_n + ((lane >> 4) << 3) + (lane & 7)) * 80
                        + (uint32_t)((lane >> 3) & 1) * 16;

    float acc[2][8][4];
    #pragma unroll
    for (int i = 0; i < 2; i++)
        #pragma unroll
        for (int j = 0; j < 8; j++)
            #pragma unroll
            for (int k = 0; k < 4; k++) acc[i][j][k] = 0.0f;

    for (int c = 0; c < Dc / 32; c++) {
        const int k0 = c * 32;
        __syncthreads();
        *(uint4*)dA        = *(const uint4*)(pA + k0);
        *(uint4*)(dA + 16) = *(const uint4*)(pA + k0 + 8);
        *(uint4*)dB        = *(const uint4*)(pB + k0);
        *(uint4*)(dB + 16) = *(const uint4*)(pB + k0 + 8);
        __syncthreads();
        #pragma unroll
        for (int ks = 0; ks < 2; ks++) {
            uint32_t a[2][4];
            LDSM4(a[0][0], a[0][1], a[0][2], a[0][3], uA + offA + ks * 32);
            LDSM4(a[1][0], a[1][1], a[1][2], a[1][3], uA + offA + 1280 + ks * 32);
            uint32_t b[8][2];
            #pragma unroll
            for (int jp = 0; jp < 4; jp++) {
                LDSM4(b[2*jp][0], b[2*jp][1], b[2*jp+1][0], b[2*jp+1][1],
                      uB + offB + (uint32_t)jp * 1280 + ks * 32);
            }
            #pragma unroll
            for (int mt = 0; mt < 2; mt++)
                #pragma unroll
                for (int nj = 0; nj < 8; nj++)
                    MMA_BF16(acc[mt][nj], a[mt], b[nj]);
        }
    }

    const int qr = lane >> 2;
    const int qc = (lane & 3) * 2;
    #pragma unroll
    for (int mt = 0; mt < 2; mt++) {
        unsigned long long b0 = 0ULL, b1 = 0ULL;
        #pragma unroll
        for (int nj = 0; nj < 8; nj++) {
            int ln = warp_n + nj * 8 + qc;
            #pragma unroll
            for (int p = 0; p < 2; p++) {
                int l = ln + p;
                if (s_act[l]) {
                    unsigned long long key2 = 0xFFFFFFFFu - (unsigned)(n0 + l);
                    float s0 = acc[mt][nj][p] * s_binv[l];
                    unsigned long long q0 = ((unsigned long long)enc_f(s0) << 32) | key2;
                    if (q0 > b0) b0 = q0;
                    float s1 = acc[mt][nj][2 + p] * s_binv[l];
                    unsigned long long q1 = ((unsigned long long)enc_f(s1) << 32) | key2;
                    if (q1 > b1) b1 = q1;
                }
            }
        }
        unsigned long long t;
        t = __shfl_xor_sync(0xffffffffu, b0, 1); if (t > b0) b0 = t;
        t = __shfl_xor_sync(0xffffffffu, b0, 2); if (t > b0) b0 = t;
        t = __shfl_xor_sync(0xffffffffu, b1, 1); if (t > b1) b1 = t;
        t = __shfl_xor_sync(0xffffffffu, b1, 2); if (t > b1) b1 = t;
        if ((lane & 3) == 0) {
            if (b0) atomicMax(&g_best[m0 + warp_m + mt * 16 + qr], b0);
            if (b1) atomicMax(&g_best[m0 + warp_m + mt * 16 + 8 + qr], b1);
        }
    }
}

// ---------------- finalize ----------------
__global__ __launch_bounds__(256) void finalize1_kernel(
    const float* __restrict__ bg2, const float* __restrict__ bp2,
    float* __restrict__ out_obs, float* __restrict__ out_meaning, int write_extra)
{
    __shared__ float sred[256];
    __shared__ float s_pm, s_inv, s_rinv;
    int t = blockIdx.x;
    int d = threadIdx.x;
    float v = g_obs_mean[(size_t)t * Dc + d];

    sred[d] = v * v;
    __syncthreads();
    for (int s = 128; s > 0; s >>= 1) {
        if (d < s) sred[d] += sred[d + s];
        __syncthreads();
    }
    if (d == 0) {
        float pm = 0.0f;
        float bg2v = bg2[0], bp2v = bp2[0];
        #pragma unroll
        for (int b = 0; b < Bc; b++) {
            int row = b * Tc + t;
            float gl = bg2v, pl = bp2v;
            #pragma unroll
            for (int jt = 0; jt < 4; jt++) gl += g_part[jt * MGP + row];
            #pragma unroll
            for (int jt = 4; jt < 8; jt++) pl += g_part[jt * MGP + row];
            pm += sigmoidf_(gl) * softplusf_(pl);
        }
        pm *= 0.25f;
        s_pm = pm;
        s_inv = 1.0f / fmaxf(sqrtf(sred[0]), EPSC);
    }
    __syncthreads();
    float ob = v * s_inv * s_pm;
    out_obs[(size_t)t * Dc + d] = ob;

    __syncthreads();
    sred[d] = ob * ob;
    __syncthreads();
    for (int s = 128; s > 0; s >>= 1) {
        if (d < s) sred[d] += sred[d + s];
        __syncthreads();
    }
    if (d == 0) {
        float rr = sqrtf(sred[0]);
        g_rad[t] = rr;
        s_rinv = 1.0f / fmaxf(rr, EPSC);
        if (write_extra) out_meaning[t] = (rr > 0.05f) ? 1.0f : 0.0f;
    }
    __syncthreads();
    g_oangb[(size_t)t * Dc + d] = __float2bfloat16_rn(ob * s_rinv);
}

__global__ void init_best_kernel() {
    int i = blockIdx.x * blockDim.x + threadIdx.x;
    if (i < Tc) g_best[i] = 0ULL;
}

__global__ void finalize2_kernel(float* __restrict__ out_sims, float* __restrict__ out_slots) {
    int t = blockIdx.x * blockDim.x + threadIdx.x;
    if (t >= Tc) return;
    unsigned long long b = g_best[t];
    float sim = 0.0f;
    int idx = -1;
    bool has = (b != 0ULL);
    if (has) {
        sim = dec_f((unsigned)(b >> 32));
        idx = (int)(0xFFFFFFFFu - (unsigned)(b & 0xFFFFFFFFu));
    }
    bool matched = has && (g_rad[t] > 0.05f) && (sim > 0.5f);
    out_sims[t]  = matched ? sim : 0.0f;
    out_slots[t] = matched ? (float)idx : -1.0f;
}

// ---------------- launcher ----------------
extern "C" void kernel_launch(void* const* d_in, const int* in_sizes, int n_in,
                              void* d_out, int out_size)
{
    const float* hidden  = (const float*)d_in[0];
    const float* beliefs = (const float*)d_in[1];
    const void*  maskp   = d_in[2];
    const float* W_obs   = (const float*)d_in[3];
    const float* W_g1    = (const float*)d_in[4];
    const float* b_g1    = (const float*)d_in[5];
    const float* W_g2    = (const float*)d_in[6];
    const float* b_g2    = (const float*)d_in[7];
    const float* W_p1    = (const float*)d_in[8];
    const float* b_p1    = (const float*)d_in[9];
    const float* W_p2    = (const float*)d_in[10];
    const float* b_p2    = (const float*)d_in[11];
    float* out = (float*)d_out;

    const size_t base = (size_t)Tc * Dc;
    const int write_extra = (out_size >= (int)(base + 3 * Tc)) ? 1 : 0;
    float* out_obs     = out;
    float* out_sims    = out + base;
    float* out_slots   = out + base + Tc;
    float* out_meaning = out + base + 2 * Tc;

    prep_hidden_kernel<<<(Tc * 512) / 256, 256>>>(hidden);
    prep_weights_kernel<<<(1280 * 512) / 256, 256>>>(W_g1, W_p1, W_obs);
    prep_small_kernel<<<4, 256>>>(b_g1, b_p1, W_g2, W_p2);
    prep_beliefs_kernel<<<((size_t)Nc * Dc / 4) / 256, 256>>>(beliefs);
    detect_mask_kernel<<<1, 256>>>((const unsigned char*)maskp, Nc);
    convert_mask_kernel<<<Nc / 256, 256>>>(maskp);
    binv_kernel<<<Nc / 8, 256>>>(beliefs);

    gp_mma_kernel<<<dim3(8, MGP / 128), 256>>>();
    obs_mma_kernel<<<dim3(2, Tc / 128), 256>>>();
    finalize1_kernel<<<Tc, 256>>>(b_g2, b_p2, out_obs, out_meaning, write_extra);

    init_best_kernel<<<Tc / 256, 256>>>();
    sims_mma_kernel<<<dim3(Nc / 128, Tc / 128), 256>>>();
    if (write_extra) {
        finalize2_kernel<<<Tc / 256, 256>>>(out_sims, out_slots);
    }
}

// round 4
// speedup vs baseline: 3.0466x; 1.3619x over previous
#include <cuda_runtime.h>
#include <cuda_bf16.h>
#include <cstdint>

#define Bc 4
#define Tc 4096
#define Hc 2048
#define Dc 256
#define Nc 32768
#define MGP (Bc*Tc)
#define EPSC 1e-8f

// ---------------- device scratch ----------------
__device__ __nv_bfloat16 g_Ahi[(size_t)MGP * Hc];
__device__ __nv_bfloat16 g_Alo[(size_t)MGP * Hc];
__device__ __nv_bfloat16 g_Hmhi[(size_t)Tc * Hc];
__device__ __nv_bfloat16 g_Hmlo[(size_t)Tc * Hc];
__device__ __nv_bfloat16 g_Wchi[(size_t)1024 * Hc];
__device__ __nv_bfloat16 g_Wclo[(size_t)1024 * Hc];
__device__ __nv_bfloat16 g_Wohi[(size_t)Dc * Hc];
__device__ __nv_bfloat16 g_Wolo[(size_t)Dc * Hc];
__device__ __nv_bfloat16 g_Bb[(size_t)Nc * Dc];
__device__ __nv_bfloat16 g_oangb[(size_t)Tc * Dc];
__device__ float g_bc1[1024];
__device__ float g_wc2[1024];
__device__ float g_obs_mean[(size_t)Tc * Dc];
__device__ float g_part[8 * MGP];
__device__ float g_binv[Nc];
__device__ unsigned char g_active[Nc];
__device__ unsigned long long g_best[Tc];
__device__ float g_rad[Tc];
__device__ int g_fmt;

// ---------------- helpers ----------------
__device__ __forceinline__ uint32_t smem_u32(const void* p) {
    uint32_t a;
    asm("{ .reg .u64 t; cvta.to.shared.u64 t, %1; cvt.u32.u64 %0, t; }" : "=r"(a) : "l"(p));
    return a;
}
#define LDSM4(R0, R1, R2, R3, A) \
    asm volatile("ldmatrix.sync.aligned.m8n8.x4.shared.b16 {%0,%1,%2,%3}, [%4];" \
        : "=r"(R0), "=r"(R1), "=r"(R2), "=r"(R3) : "r"(A))
#define MMA_BF16(D, A, B) \
    asm volatile("mma.sync.aligned.m16n8k16.row.col.f32.bf16.bf16.f32 " \
        "{%0,%1,%2,%3}, {%4,%5,%6,%7}, {%8,%9}, {%0,%1,%2,%3};" \
        : "+f"((D)[0]), "+f"((D)[1]), "+f"((D)[2]), "+f"((D)[3]) \
        : "r"((A)[0]), "r"((A)[1]), "r"((A)[2]), "r"((A)[3]), "r"((B)[0]), "r"((B)[1]))
#define CP16(DST, SRC) \
    asm volatile("cp.async.cg.shared.global [%0], [%1], 16;" :: "r"(DST), "l"(SRC) : "memory")
#define CP_COMMIT() asm volatile("cp.async.commit_group;" ::: "memory")
#define CP_WAIT2()  asm volatile("cp.async.wait_group 2;" ::: "memory")

__device__ __forceinline__ unsigned enc_f(float f) {
    unsigned u = __float_as_uint(f);
    return (u & 0x80000000u) ? ~u : (u | 0x80000000u);
}
__device__ __forceinline__ float dec_f(unsigned e) {
    unsigned u = (e & 0x80000000u) ? (e ^ 0x80000000u) : ~e;
    return __uint_as_float(u);
}
__device__ __forceinline__ float sigmoidf_(float x) { return 1.0f / (1.0f + expf(-x)); }
__device__ __forceinline__ float softplusf_(float x) {
    return fmaxf(x, 0.0f) + log1pf(expf(-fabsf(x)));
}
__device__ __forceinline__ void split_store(__nv_bfloat16* hi, __nv_bfloat16* lo, float4 v) {
    __nv_bfloat16 h0 = __float2bfloat16_rn(v.x);
    __nv_bfloat16 h1 = __float2bfloat16_rn(v.y);
    __nv_bfloat16 h2 = __float2bfloat16_rn(v.z);
    __nv_bfloat16 h3 = __float2bfloat16_rn(v.w);
    __nv_bfloat16 l0 = __float2bfloat16_rn(v.x - __bfloat162float(h0));
    __nv_bfloat16 l1 = __float2bfloat16_rn(v.y - __bfloat162float(h1));
    __nv_bfloat16 l2 = __float2bfloat16_rn(v.z - __bfloat162float(h2));
    __nv_bfloat16 l3 = __float2bfloat16_rn(v.w - __bfloat162float(h3));
    ((__nv_bfloat162*)hi)[0] = __nv_bfloat162(h0, h1);
    ((__nv_bfloat162*)hi)[1] = __nv_bfloat162(h2, h3);
    ((__nv_bfloat162*)lo)[0] = __nv_bfloat162(l0, l1);
    ((__nv_bfloat162*)lo)[1] = __nv_bfloat162(l2, l3);
}

// ---------------- prep kernels ----------------
__global__ void prep_hidden_kernel(const float* __restrict__ hidden) {
    int idx = blockIdx.x * blockDim.x + threadIdx.x;
    int t = idx >> 9, h = (idx & 511) * 4;
    float4 acc = make_float4(0, 0, 0, 0);
    #pragma unroll
    for (int b = 0; b < Bc; b++) {
        size_t row = (size_t)(b * Tc + t);
        float4 v = *(const float4*)(hidden + row * Hc + h);
        split_store(g_Ahi + row * Hc + h, g_Alo + row * Hc + h, v);
        acc.x += v.x; acc.y += v.y; acc.z += v.z; acc.w += v.w;
    }
    acc.x *= 0.25f; acc.y *= 0.25f; acc.z *= 0.25f; acc.w *= 0.25f;
    split_store(g_Hmhi + (size_t)t * Hc + h, g_Hmlo + (size_t)t * Hc + h, acc);
}

__global__ void prep_weights_kernel(const float* __restrict__ Wg1, const float* __restrict__ Wp1,
                                    const float* __restrict__ Wobs) {
    int idx = blockIdx.x * blockDim.x + threadIdx.x;
    int row = idx >> 9, h = (idx & 511) * 4;
    if (row < 1024) {
        const float* src = (row < 512) ? (Wg1 + (size_t)row * Hc) : (Wp1 + (size_t)(row - 512) * Hc);
        float4 v = *(const float4*)(src + h);
        split_store(g_Wchi + (size_t)row * Hc + h, g_Wclo + (size_t)row * Hc + h, v);
    } else {
        int r2 = row - 1024;
        float4 v = *(const float4*)(Wobs + (size_t)r2 * Hc + h);
        split_store(g_Wohi + (size_t)r2 * Hc + h, g_Wolo + (size_t)r2 * Hc + h, v);
    }
}

__global__ void prep_small_kernel(const float* __restrict__ bg1, const float* __restrict__ bp1,
                                  const float* __restrict__ Wg2, const float* __restrict__ Wp2) {
    int i = blockIdx.x * blockDim.x + threadIdx.x;
    if (i < 1024) {
        g_bc1[i] = (i < 512) ? bg1[i] : bp1[i - 512];
        g_wc2[i] = (i < 512) ? Wg2[i] : Wp2[i - 512];
    }
}

__global__ void prep_beliefs_kernel(const float* __restrict__ beliefs) {
    int idx = blockIdx.x * blockDim.x + threadIdx.x;
    size_t e = (size_t)idx * 4;
    float4 v = *(const float4*)(beliefs + e);
    ((__nv_bfloat162*)(g_Bb + e))[0] = __nv_bfloat162(__float2bfloat16_rn(v.x), __float2bfloat16_rn(v.y));
    ((__nv_bfloat162*)(g_Bb + e))[1] = __nv_bfloat162(__float2bfloat16_rn(v.z), __float2bfloat16_rn(v.w));
}

__global__ void detect_mask_kernel(const unsigned char* __restrict__ m, int nbytes) {
    __shared__ int weird, off4;
    if (threadIdx.x == 0) { weird = 0; off4 = 0; }
    __syncthreads();
    for (int i = threadIdx.x; i < nbytes; i += blockDim.x) {
        unsigned char c = m[i];
        if (c > 1) atomicOr(&weird, 1);
        if (c != 0 && (i & 3)) atomicOr(&off4, 1);
    }
    __syncthreads();
    if (threadIdx.x == 0) g_fmt = weird ? 2 : (off4 ? 1 : 0);
}
__global__ void convert_mask_kernel(const void* __restrict__ m) {
    int i = blockIdx.x * blockDim.x + threadIdx.x;
    if (i >= Nc) return;
    int fmt = g_fmt;
    unsigned char a;
    if (fmt == 0)      a = (((const int*)m)[i] != 0);
    else if (fmt == 1) a = (((const unsigned char*)m)[i] != 0);
    else               a = (((const float*)m)[i] != 0.0f);
    g_active[i] = a;
}
__global__ void binv_kernel(const float* __restrict__ beliefs) {
    int row = blockIdx.x * 8 + (threadIdx.x >> 5);
    int lane = threadIdx.x & 31;
    const float4* p = reinterpret_cast<const float4*>(beliefs + (size_t)row * Dc);
    float s = 0.0f;
    #pragma unroll
    for (int r = 0; r < 2; r++) {
        float4 v = p[lane + r * 32];
        s += v.x * v.x + v.y * v.y + v.z * v.z + v.w * v.w;
    }
    #pragma unroll
    for (int o = 16; o > 0; o >>= 1) s += __shfl_down_sync(0xffffffffu, s, o);
    if (lane == 0) g_binv[row] = 1.0f / fmaxf(sqrtf(s), EPSC);
}

// ============ gate/prec GEMM: pipelined cp.async, split-bf16, K=2048 ============
// block 128x128, 8 warps, K-chunk 32, 3 stages. Stage = {Ah,Al,Bh,Bl} @ 10240 B each.
#define GP_STG 40960
__global__ __launch_bounds__(256, 1) void gp_mma_kernel() {
    extern __shared__ __align__(128) char dsm[];
    __shared__ float s_b1[128], s_w2[128], s_red[128];

    const int tid = threadIdx.x, lane = tid & 31, wid = tid >> 5;
    const int bx = blockIdx.x;
    const int m0 = blockIdx.y * 128;
    const int nbase = bx * 128;
    const int warp_m = (wid >> 1) * 32;
    const int warp_n = (wid & 1) * 64;
    const uint32_t sbase = smem_u32(dsm);

    if (tid < 128) {
        s_b1[tid] = g_bc1[nbase + tid];
        s_w2[tid] = g_wc2[nbase + tid];
        s_red[tid] = 0.0f;
    }

    const int r = tid >> 1, seg = tid & 1;
    const char* pAh = (const char*)(g_Ahi + (size_t)(m0 + r) * Hc + seg * 16);
    const char* pAl = (const char*)(g_Alo + (size_t)(m0 + r) * Hc + seg * 16);
    const char* pBh = (const char*)(g_Wchi + (size_t)(nbase + r) * Hc + seg * 16);
    const char* pBl = (const char*)(g_Wclo + (size_t)(nbase + r) * Hc + seg * 16);
    const uint32_t dOff = (uint32_t)r * 80 + (uint32_t)seg * 32;

    const uint32_t offA = (uint32_t)(warp_m + (lane & 15)) * 80 + (uint32_t)(lane >> 4) * 16;
    const uint32_t offB = (uint32_t)(warp_n + ((lane >> 4) << 3) + (lane & 7)) * 80
                        + (uint32_t)((lane >> 3) & 1) * 16;

    float acc[2][8][4];
    #pragma unroll
    for (int i = 0; i < 2; i++)
        #pragma unroll
        for (int j = 0; j < 8; j++)
            #pragma unroll
            for (int k = 0; k < 4; k++) acc[i][j][k] = 0.0f;

    // prologue: stages for chunks 0,1
    #pragma unroll
    for (int c = 0; c < 2; c++) {
        const size_t kb = (size_t)c * 64;
        const uint32_t st = sbase + c * GP_STG + dOff;
        CP16(st,              pAh + kb); CP16(st + 16,             pAh + kb + 16);
        CP16(st + 10240,      pAl + kb); CP16(st + 10240 + 16,     pAl + kb + 16);
        CP16(st + 20480,      pBh + kb); CP16(st + 20480 + 16,     pBh + kb + 16);
        CP16(st + 30720,      pBl + kb); CP16(st + 30720 + 16,     pBl + kb + 16);
        CP_COMMIT();
    }

    for (int c = 0; c < 64; c++) {
        if (c + 2 < 64) {
            const size_t kb = (size_t)(c + 2) * 64;
            const uint32_t st = sbase + ((c + 2) % 3) * GP_STG + dOff;
            CP16(st,              pAh + kb); CP16(st + 16,             pAh + kb + 16);
            CP16(st + 10240,      pAl + kb); CP16(st + 10240 + 16,     pAl + kb + 16);
            CP16(st + 20480,      pBh + kb); CP16(st + 20480 + 16,     pBh + kb + 16);
            CP16(st + 30720,      pBl + kb); CP16(st + 30720 + 16,     pBl + kb + 16);
        }
        CP_COMMIT();
        CP_WAIT2();
        __syncthreads();
        const uint32_t uS = sbase + (c % 3) * GP_STG;
        const uint32_t uAh = uS, uAl = uS + 10240, uBh = uS + 20480, uBl = uS + 30720;
        #pragma unroll
        for (int ks = 0; ks < 2; ks++) {
            uint32_t ah[2][4], al[2][4];
            LDSM4(ah[0][0], ah[0][1], ah[0][2], ah[0][3], uAh + offA + ks * 32);
            LDSM4(ah[1][0], ah[1][1], ah[1][2], ah[1][3], uAh + offA + 1280 + ks * 32);
            LDSM4(al[0][0], al[0][1], al[0][2], al[0][3], uAl + offA + ks * 32);
            LDSM4(al[1][0], al[1][1], al[1][2], al[1][3], uAl + offA + 1280 + ks * 32);
            uint32_t bh[8][2], bl[8][2];
            #pragma unroll
            for (int jp = 0; jp < 4; jp++) {
                LDSM4(bh[2*jp][0], bh[2*jp][1], bh[2*jp+1][0], bh[2*jp+1][1],
                      uBh + offB + (uint32_t)jp * 1280 + ks * 32);
                LDSM4(bl[2*jp][0], bl[2*jp][1], bl[2*jp+1][0], bl[2*jp+1][1],
                      uBl + offB + (uint32_t)jp * 1280 + ks * 32);
            }
            #pragma unroll
            for (int mt = 0; mt < 2; mt++)
                #pragma unroll
                for (int nj = 0; nj < 8; nj++) {
                    MMA_BF16(acc[mt][nj], ah[mt], bh[nj]);
                    MMA_BF16(acc[mt][nj], ah[mt], bl[nj]);
                    MMA_BF16(acc[mt][nj], al[mt], bh[nj]);
                }
        }
        __syncthreads();
    }

    // fused relu + rank-1 epilogue
    const int qr = lane >> 2;
    const int qc = (lane & 3) * 2;
    #pragma unroll
    for (int mt = 0; mt < 2; mt++) {
        float p0 = 0.0f, p1 = 0.0f;
        #pragma unroll
        for (int nj = 0; nj < 8; nj++) {
            int col = warp_n + nj * 8 + qc;
            p0 += fmaxf(acc[mt][nj][0] + s_b1[col], 0.0f) * s_w2[col]
                + fmaxf(acc[mt][nj][1] + s_b1[col + 1], 0.0f) * s_w2[col + 1];
            p1 += fmaxf(acc[mt][nj][2] + s_b1[col], 0.0f) * s_w2[col]
                + fmaxf(acc[mt][nj][3] + s_b1[col + 1], 0.0f) * s_w2[col + 1];
        }
        p0 += __shfl_xor_sync(0xffffffffu, p0, 1);
        p0 += __shfl_xor_sync(0xffffffffu, p0, 2);
        p1 += __shfl_xor_sync(0xffffffffu, p1, 1);
        p1 += __shfl_xor_sync(0xffffffffu, p1, 2);
        if ((lane & 3) == 0) {
            atomicAdd(&s_red[warp_m + mt * 16 + qr], p0);
            atomicAdd(&s_red[warp_m + mt * 16 + 8 + qr], p1);
        }
    }
    __syncthreads();
    if (tid < 128) g_part[bx * MGP + m0 + tid] = s_red[tid];
}

// ============ obs GEMM: pipelined, split-bf16 on batch-mean hidden ============
__global__ __launch_bounds__(256, 1) void obs_mma_kernel() {
    extern __shared__ __align__(128) char dsm[];

    const int tid = threadIdx.x, lane = tid & 31, wid = tid >> 5;
    const int m0 = blockIdx.y * 128;
    const int nbase = blockIdx.x * 128;
    const int warp_m = (wid >> 1) * 32;
    const int warp_n = (wid & 1) * 64;
    const uint32_t sbase = smem_u32(dsm);

    const int r = tid >> 1, seg = tid & 1;
    const char* pAh = (const char*)(g_Hmhi + (size_t)(m0 + r) * Hc + seg * 16);
    const char* pAl = (const char*)(g_Hmlo + (size_t)(m0 + r) * Hc + seg * 16);
    const char* pBh = (const char*)(g_Wohi + (size_t)(nbase + r) * Hc + seg * 16);
    const char* pBl = (const char*)(g_Wolo + (size_t)(nbase + r) * Hc + seg * 16);
    const uint32_t dOff = (uint32_t)r * 80 + (uint32_t)seg * 32;

    const uint32_t offA = (uint32_t)(warp_m + (lane & 15)) * 80 + (uint32_t)(lane >> 4) * 16;
    const uint32_t offB = (uint32_t)(warp_n + ((lane >> 4) << 3) + (lane & 7)) * 80
                        + (uint32_t)((lane >> 3) & 1) * 16;

    float acc[2][8][4];
    #pragma unroll
    for (int i = 0; i < 2; i++)
        #pragma unroll
        for (int j = 0; j < 8; j++)
            #pragma unroll
            for (int k = 0; k < 4; k++) acc[i][j][k] = 0.0f;

    #pragma unroll
    for (int c = 0; c < 2; c++) {
        const size_t kb = (size_t)c * 64;
        const uint32_t st = sbase + c * GP_STG + dOff;
        CP16(st,              pAh + kb); CP16(st + 16,             pAh + kb + 16);
        CP16(st + 10240,      pAl + kb); CP16(st + 10240 + 16,     pAl + kb + 16);
        CP16(st + 20480,      pBh + kb); CP16(st + 20480 + 16,     pBh + kb + 16);
        CP16(st + 30720,      pBl + kb); CP16(st + 30720 + 16,     pBl + kb + 16);
        CP_COMMIT();
    }

    for (int c = 0; c < 64; c++) {
        if (c + 2 < 64) {
            const size_t kb = (size_t)(c + 2) * 64;
            const uint32_t st = sbase + ((c + 2) % 3) * GP_STG + dOff;
            CP16(st,              pAh + kb); CP16(st + 16,             pAh + kb + 16);
            CP16(st + 10240,      pAl + kb); CP16(st + 10240 + 16,     pAl + kb + 16);
            CP16(st + 20480,      pBh + kb); CP16(st + 20480 + 16,     pBh + kb + 16);
            CP16(st + 30720,      pBl + kb); CP16(st + 30720 + 16,     pBl + kb + 16);
        }
        CP_COMMIT();
        CP_WAIT2();
        __syncthreads();
        const uint32_t uS = sbase + (c % 3) * GP_STG;
        const uint32_t uAh = uS, uAl = uS + 10240, uBh = uS + 20480, uBl = uS + 30720;
        #pragma unroll
        for (int ks = 0; ks < 2; ks++) {
            uint32_t ah[2][4], al[2][4];
            LDSM4(ah[0][0], ah[0][1], ah[0][2], ah[0][3], uAh + offA + ks * 32);
            LDSM4(ah[1][0], ah[1][1], ah[1][2], ah[1][3], uAh + offA + 1280 + ks * 32);
            LDSM4(al[0][0], al[0][1], al[0][2], al[0][3], uAl + offA + ks * 32);
            LDSM4(al[1][0], al[1][1], al[1][2], al[1][3], uAl + offA + 1280 + ks * 32);
            uint32_t bh[8][2], bl[8][2];
            #pragma unroll
            for (int jp = 0; jp < 4; jp++) {
                LDSM4(bh[2*jp][0], bh[2*jp][1], bh[2*jp+1][0], bh[2*jp+1][1],
                      uBh + offB + (uint32_t)jp * 1280 + ks * 32);
                LDSM4(bl[2*jp][0], bl[2*jp][1], bl[2*jp+1][0], bl[2*jp+1][1],
                      uBl + offB + (uint32_t)jp * 1280 + ks * 32);
            }
            #pragma unroll
            for (int mt = 0; mt < 2; mt++)
                #pragma unroll
                for (int nj = 0; nj < 8; nj++) {
                    MMA_BF16(acc[mt][nj], ah[mt], bh[nj]);
                    MMA_BF16(acc[mt][nj], ah[mt], bl[nj]);
                    MMA_BF16(acc[mt][nj], al[mt], bh[nj]);
                }
        }
        __syncthreads();
    }

    const int qr = lane >> 2;
    const int qc = (lane & 3) * 2;
    #pragma unroll
    for (int mt = 0; mt < 2; mt++)
        #pragma unroll
        for (int nj = 0; nj < 8; nj++) {
            int row = m0 + warp_m + mt * 16 + qr;
            int col = nbase + warp_n + nj * 8 + qc;
            *(float2*)(g_obs_mean + (size_t)row * Dc + col) = make_float2(acc[mt][nj][0], acc[mt][nj][1]);
            *(float2*)(g_obs_mean + (size_t)(row + 8) * Dc + col) = make_float2(acc[mt][nj][2], acc[mt][nj][3]);
        }
}

// ============ sims GEMM: pipelined bf16 + masked max/argmax epilogue ============
#define SM_STG 20480
__global__ __launch_bounds__(256, 1) void sims_mma_kernel() {
    extern __shared__ __align__(128) char dsm[];
    __shared__ float s_binv[128];
    __shared__ unsigned char s_act[128];

    const int tid = threadIdx.x, lane = tid & 31, wid = tid >> 5;
    const int n0 = blockIdx.x * 128;
    const int m0 = blockIdx.y * 128;
    const int warp_m = (wid >> 1) * 32;
    const int warp_n = (wid & 1) * 64;
    const uint32_t sbase = smem_u32(dsm);

    if (tid < 128) { s_binv[tid] = g_binv[n0 + tid]; s_act[tid] = g_active[n0 + tid]; }

    const int r = tid >> 1, seg = tid & 1;
    const char* pA = (const char*)(g_oangb + (size_t)(m0 + r) * Dc + seg * 16);
    const char* pB = (const char*)(g_Bb + (size_t)(n0 + r) * Dc + seg * 16);
    const uint32_t dOff = (uint32_t)r * 80 + (uint32_t)seg * 32;

    const uint32_t offA = (uint32_t)(warp_m + (lane & 15)) * 80 + (uint32_t)(lane >> 4) * 16;
    const uint32_t offB = (uint32_t)(warp_n + ((lane >> 4) << 3) + (lane & 7)) * 80
                        + (uint32_t)((lane >> 3) & 1) * 16;

    float acc[2][8][4];
    #pragma unroll
    for (int i = 0; i < 2; i++)
        #pragma unroll
        for (int j = 0; j < 8; j++)
            #pragma unroll
            for (int k = 0; k < 4; k++) acc[i][j][k] = 0.0f;

    #pragma unroll
    for (int c = 0; c < 2; c++) {
        const size_t kb = (size_t)c * 64;
        const uint32_t st = sbase + c * SM_STG + dOff;
        CP16(st,         pA + kb); CP16(st + 16,         pA + kb + 16);
        CP16(st + 10240, pB + kb); CP16(st + 10240 + 16, pB + kb + 16);
        CP_COMMIT();
    }

    for (int c = 0; c < 8; c++) {
        if (c + 2 < 8) {
            const size_t kb = (size_t)(c + 2) * 64;
            const uint32_t st = sbase + ((c + 2) % 3) * SM_STG + dOff;
            CP16(st,         pA + kb); CP16(st + 16,         pA + kb + 16);
            CP16(st + 10240, pB + kb); CP16(st + 10240 + 16, pB + kb + 16);
        }
        CP_COMMIT();
        CP_WAIT2();
        __syncthreads();
        const uint32_t uS = sbase + (c % 3) * SM_STG;
        const uint32_t uA = uS, uB = uS + 10240;
        #pragma unroll
        for (int ks = 0; ks < 2; ks++) {
            uint32_t a[2][4];
            LDSM4(a[0][0], a[0][1], a[0][2], a[0][3], uA + offA + ks * 32);
            LDSM4(a[1][0], a[1][1], a[1][2], a[1][3], uA + offA + 1280 + ks * 32);
            uint32_t b[8][2];
            #pragma unroll
            for (int jp = 0; jp < 4; jp++) {
                LDSM4(b[2*jp][0], b[2*jp][1], b[2*jp+1][0], b[2*jp+1][1],
                      uB + offB + (uint32_t)jp * 1280 + ks * 32);
            }
            #pragma unroll
            for (int mt = 0; mt < 2; mt++)
                #pragma unroll
                for (int nj = 0; nj < 8; nj++)
                    MMA_BF16(acc[mt][nj], a[mt], b[nj]);
        }
        __syncthreads();
    }

    const int qr = lane >> 2;
    const int qc = (lane & 3) * 2;
    #pragma unroll
    for (int mt = 0; mt < 2; mt++) {
        unsigned long long b0 = 0ULL, b1 = 0ULL;
        #pragma unroll
        for (int nj = 0; nj < 8; nj++) {
            int ln = warp_n + nj * 8 + qc;
            #pragma unroll
            for (int p = 0; p < 2; p++) {
                int l = ln + p;
                if (s_act[l]) {
                    unsigned long long key2 = 0xFFFFFFFFu - (unsigned)(n0 + l);
                    float s0 = acc[mt][nj][p] * s_binv[l];
                    unsigned long long q0 = ((unsigned long long)enc_f(s0) << 32) | key2;
                    if (q0 > b0) b0 = q0;
                    float s1 = acc[mt][nj][2 + p] * s_binv[l];
                    unsigned long long q1 = ((unsigned long long)enc_f(s1) << 32) | key2;
                    if (q1 > b1) b1 = q1;
                }
            }
        }
        unsigned long long t;
        t = __shfl_xor_sync(0xffffffffu, b0, 1); if (t > b0) b0 = t;
        t = __shfl_xor_sync(0xffffffffu, b0, 2); if (t > b0) b0 = t;
        t = __shfl_xor_sync(0xffffffffu, b1, 1); if (t > b1) b1 = t;
        t = __shfl_xor_sync(0xffffffffu, b1, 2); if (t > b1) b1 = t;
        if ((lane & 3) == 0) {
            if (b0) atomicMax(&g_best[m0 + warp_m + mt * 16 + qr], b0);
            if (b1) atomicMax(&g_best[m0 + warp_m + mt * 16 + 8 + qr], b1);
        }
    }
}

// ---------------- finalize ----------------
__global__ __launch_bounds__(256) void finalize1_kernel(
    const float* __restrict__ bg2, const float* __restrict__ bp2,
    float* __restrict__ out_obs, float* __restrict__ out_meaning, int write_extra)
{
    __shared__ float sred[256];
    __shared__ float s_pm, s_inv, s_rinv;
    int t = blockIdx.x;
    int d = threadIdx.x;
    float v = g_obs_mean[(size_t)t * Dc + d];

    sred[d] = v * v;
    __syncthreads();
    for (int s = 128; s > 0; s >>= 1) {
        if (d < s) sred[d] += sred[d + s];
        __syncthreads();
    }
    if (d == 0) {
        float pm = 0.0f;
        float bg2v = bg2[0], bp2v = bp2[0];
        #pragma unroll
        for (int b = 0; b < Bc; b++) {
            int row = b * Tc + t;
            float gl = bg2v, pl = bp2v;
            #pragma unroll
            for (int jt = 0; jt < 4; jt++) gl += g_part[jt * MGP + row];
            #pragma unroll
            for (int jt = 4; jt < 8; jt++) pl += g_part[jt * MGP + row];
            pm += sigmoidf_(gl) * softplusf_(pl);
        }
        pm *= 0.25f;
        s_pm = pm;
        s_inv = 1.0f / fmaxf(sqrtf(sred[0]), EPSC);
    }
    __syncthreads();
    float ob = v * s_inv * s_pm;
    out_obs[(size_t)t * Dc + d] = ob;

    __syncthreads();
    sred[d] = ob * ob;
    __syncthreads();
    for (int s = 128; s > 0; s >>= 1) {
        if (d < s) sred[d] += sred[d + s];
        __syncthreads();
    }
    if (d == 0) {
        float rr = sqrtf(sred[0]);
        g_rad[t] = rr;
        s_rinv = 1.0f / fmaxf(rr, EPSC);
        if (write_extra) out_meaning[t] = (rr > 0.05f) ? 1.0f : 0.0f;
    }
    __syncthreads();
    g_oangb[(size_t)t * Dc + d] = __float2bfloat16_rn(ob * s_rinv);
}

__global__ void init_best_kernel() {
    int i = blockIdx.x * blockDim.x + threadIdx.x;
    if (i < Tc) g_best[i] = 0ULL;
}

__global__ void finalize2_kernel(float* __restrict__ out_sims, float* __restrict__ out_slots) {
    int t = blockIdx.x * blockDim.x + threadIdx.x;
    if (t >= Tc) return;
    unsigned long long b = g_best[t];
    float sim = 0.0f;
    int idx = -1;
    bool has = (b != 0ULL);
    if (has) {
        sim = dec_f((unsigned)(b >> 32));
        idx = (int)(0xFFFFFFFFu - (unsigned)(b & 0xFFFFFFFFu));
    }
    bool matched = has && (g_rad[t] > 0.05f) && (sim > 0.5f);
    out_sims[t]  = matched ? sim : 0.0f;
    out_slots[t] = matched ? (float)idx : -1.0f;
}

// ---------------- launcher ----------------
extern "C" void kernel_launch(void* const* d_in, const int* in_sizes, int n_in,
                              void* d_out, int out_size)
{
    const float* hidden  = (const float*)d_in[0];
    const float* beliefs = (const float*)d_in[1];
    const void*  maskp   = d_in[2];
    const float* W_obs   = (const float*)d_in[3];
    const float* W_g1    = (const float*)d_in[4];
    const float* b_g1    = (const float*)d_in[5];
    const float* W_g2    = (const float*)d_in[6];
    const float* b_g2    = (const float*)d_in[7];
    const float* W_p1    = (const float*)d_in[8];
    const float* b_p1    = (const float*)d_in[9];
    const float* W_p2    = (const float*)d_in[10];
    const float* b_p2    = (const float*)d_in[11];
    float* out = (float*)d_out;

    static int attr_set = 0;
    if (!attr_set) {
        cudaFuncSetAttribute(gp_mma_kernel, cudaFuncAttributeMaxDynamicSharedMemorySize, 3 * GP_STG);
        cudaFuncSetAttribute(obs_mma_kernel, cudaFuncAttributeMaxDynamicSharedMemorySize, 3 * GP_STG);
        cudaFuncSetAttribute(sims_mma_kernel, cudaFuncAttributeMaxDynamicSharedMemorySize, 3 * SM_STG);
        attr_set = 1;
    }

    const size_t base = (size_t)Tc * Dc;
    const int write_extra = (out_size >= (int)(base + 3 * Tc)) ? 1 : 0;
    float* out_obs     = out;
    float* out_sims    = out + base;
    float* out_slots   = out + base + Tc;
    float* out_meaning = out + base + 2 * Tc;

    prep_hidden_kernel<<<(Tc * 512) / 256, 256>>>(hidden);
    prep_weights_kernel<<<(1280 * 512) / 256, 256>>>(W_g1, W_p1, W_obs);
    prep_small_kernel<<<4, 256>>>(b_g1, b_p1, W_g2, W_p2);
    prep_beliefs_kernel<<<((size_t)Nc * Dc / 4) / 256, 256>>>(beliefs);
    detect_mask_kernel<<<1, 256>>>((const unsigned char*)maskp, Nc);
    convert_mask_kernel<<<Nc / 256, 256>>>(maskp);
    binv_kernel<<<Nc / 8, 256>>>(beliefs);
    init_best_kernel<<<Tc / 256, 256>>>();

    gp_mma_kernel<<<dim3(8, MGP / 128), 256, 3 * GP_STG>>>();
    obs_mma_kernel<<<dim3(2, Tc / 128), 256, 3 * GP_STG>>>();
    finalize1_kernel<<<Tc, 256>>>(b_g2, b_p2, out_obs, out_meaning, write_extra);

    sims_mma_kernel<<<dim3(Nc / 128, Tc / 128), 256, 3 * SM_STG>>>();
    if (write_extra) {
        finalize2_kernel<<<Tc / 256, 256>>>(out_sims, out_slots);
    }
}

// round 5
// speedup vs baseline: 5.2585x; 1.7260x over previous
#include <cuda_runtime.h>
#include <cuda_fp16.h>
#include <cstdint>

#define Bc 4
#define Tc 4096
#define Hc 2048
#define Dc 256
#define Nc 32768
#define MGP (Bc*Tc)
#define EPSC 1e-8f

// ---------------- device scratch ----------------
__device__ __half g_Af[(size_t)MGP * Hc];        // hidden, fp16
__device__ __half g_Hmhi[(size_t)Tc * Hc];       // batch-mean hidden hi/lo
__device__ __half g_Hmlo[(size_t)Tc * Hc];
__device__ __half g_Wcf[(size_t)1024 * Hc];      // gate+prec W1, fp16
__device__ __half g_Wohi[(size_t)Dc * Hc];       // W_obs hi/lo
__device__ __half g_Wolo[(size_t)Dc * Hc];
__device__ __half g_Bb[(size_t)Nc * Dc];         // beliefs fp16
__device__ __half g_oangb[(size_t)Tc * Dc];      // o_angles fp16
__device__ float g_bc1[1024];
__device__ float g_wc2[1024];
__device__ float g_obs_mean[(size_t)Tc * Dc];
__device__ float g_part[8 * MGP];
__device__ float g_binv[Nc];
__device__ unsigned char g_active[Nc];
__device__ unsigned long long g_best[Tc];
__device__ float g_rad[Tc];
__device__ int g_fmt;

// ---------------- helpers ----------------
__device__ __forceinline__ uint32_t smem_u32(const void* p) {
    uint32_t a;
    asm("{ .reg .u64 t; cvta.to.shared.u64 t, %1; cvt.u32.u64 %0, t; }" : "=r"(a) : "l"(p));
    return a;
}
#define LDSM4(R0, R1, R2, R3, A) \
    asm volatile("ldmatrix.sync.aligned.m8n8.x4.shared.b16 {%0,%1,%2,%3}, [%4];" \
        : "=r"(R0), "=r"(R1), "=r"(R2), "=r"(R3) : "r"(A))
#define MMA_F16(D, A, B) \
    asm volatile("mma.sync.aligned.m16n8k16.row.col.f32.f16.f16.f32 " \
        "{%0,%1,%2,%3}, {%4,%5,%6,%7}, {%8,%9}, {%0,%1,%2,%3};" \
        : "+f"((D)[0]), "+f"((D)[1]), "+f"((D)[2]), "+f"((D)[3]) \
        : "r"((A)[0]), "r"((A)[1]), "r"((A)[2]), "r"((A)[3]), "r"((B)[0]), "r"((B)[1]))
#define CP16(DST, SRC) \
    asm volatile("cp.async.cg.shared.global [%0], [%1], 16;" :: "r"(DST), "l"(SRC) : "memory")
#define CP_COMMIT() asm volatile("cp.async.commit_group;" ::: "memory")
#define CP_WAIT2()  asm volatile("cp.async.wait_group 2;" ::: "memory")

__device__ __forceinline__ unsigned enc_f(float f) {
    unsigned u = __float_as_uint(f);
    return (u & 0x80000000u) ? ~u : (u | 0x80000000u);
}
__device__ __forceinline__ float dec_f(unsigned e) {
    unsigned u = (e & 0x80000000u) ? (e ^ 0x80000000u) : ~e;
    return __uint_as_float(u);
}
__device__ __forceinline__ float sigmoidf_(float x) { return 1.0f / (1.0f + expf(-x)); }
__device__ __forceinline__ float softplusf_(float x) {
    return fmaxf(x, 0.0f) + log1pf(expf(-fabsf(x)));
}
__device__ __forceinline__ void split_store_h(__half* hi, __half* lo, float4 v) {
    __half h0 = __float2half_rn(v.x);
    __half h1 = __float2half_rn(v.y);
    __half h2 = __float2half_rn(v.z);
    __half h3 = __float2half_rn(v.w);
    __half l0 = __float2half_rn(v.x - __half2float(h0));
    __half l1 = __float2half_rn(v.y - __half2float(h1));
    __half l2 = __float2half_rn(v.z - __half2float(h2));
    __half l3 = __float2half_rn(v.w - __half2float(h3));
    ((__half2*)hi)[0] = __halves2half2(h0, h1);
    ((__half2*)hi)[1] = __halves2half2(h2, h3);
    ((__half2*)lo)[0] = __halves2half2(l0, l1);
    ((__half2*)lo)[1] = __halves2half2(l2, l3);
}
__device__ __forceinline__ void h_store4(__half* dst, float4 v) {
    ((__half2*)dst)[0] = __halves2half2(__float2half_rn(v.x), __float2half_rn(v.y));
    ((__half2*)dst)[1] = __halves2half2(__float2half_rn(v.z), __float2half_rn(v.w));
}

// ---------------- prep kernels ----------------
__global__ void prep_hidden_kernel(const float* __restrict__ hidden) {
    int idx = blockIdx.x * blockDim.x + threadIdx.x;
    int t = idx >> 9, h = (idx & 511) * 4;
    float4 acc = make_float4(0, 0, 0, 0);
    #pragma unroll
    for (int b = 0; b < Bc; b++) {
        size_t row = (size_t)(b * Tc + t);
        float4 v = *(const float4*)(hidden + row * Hc + h);
        h_store4(g_Af + row * Hc + h, v);
        acc.x += v.x; acc.y += v.y; acc.z += v.z; acc.w += v.w;
    }
    acc.x *= 0.25f; acc.y *= 0.25f; acc.z *= 0.25f; acc.w *= 0.25f;
    split_store_h(g_Hmhi + (size_t)t * Hc + h, g_Hmlo + (size_t)t * Hc + h, acc);
}

__global__ void prep_weights_kernel(const float* __restrict__ Wg1, const float* __restrict__ Wp1,
                                    const float* __restrict__ Wobs) {
    int idx = blockIdx.x * blockDim.x + threadIdx.x;
    int row = idx >> 9, h = (idx & 511) * 4;
    if (row < 1024) {
        const float* src = (row < 512) ? (Wg1 + (size_t)row * Hc) : (Wp1 + (size_t)(row - 512) * Hc);
        float4 v = *(const float4*)(src + h);
        h_store4(g_Wcf + (size_t)row * Hc + h, v);
    } else {
        int r2 = row - 1024;
        float4 v = *(const float4*)(Wobs + (size_t)r2 * Hc + h);
        split_store_h(g_Wohi + (size_t)r2 * Hc + h, g_Wolo + (size_t)r2 * Hc + h, v);
    }
}

__global__ void prep_small_kernel(const float* __restrict__ bg1, const float* __restrict__ bp1,
                                  const float* __restrict__ Wg2, const float* __restrict__ Wp2) {
    int i = blockIdx.x * blockDim.x + threadIdx.x;
    if (i < 1024) {
        g_bc1[i] = (i < 512) ? bg1[i] : bp1[i - 512];
        g_wc2[i] = (i < 512) ? Wg2[i] : Wp2[i - 512];
    }
}

__global__ void prep_beliefs_kernel(const float* __restrict__ beliefs) {
    int idx = blockIdx.x * blockDim.x + threadIdx.x;
    size_t e = (size_t)idx * 4;
    float4 v = *(const float4*)(beliefs + e);
    h_store4(g_Bb + e, v);
}

__global__ void detect_mask_kernel(const unsigned char* __restrict__ m, int nbytes) {
    __shared__ int weird, off4;
    if (threadIdx.x == 0) { weird = 0; off4 = 0; }
    __syncthreads();
    for (int i = threadIdx.x; i < nbytes; i += blockDim.x) {
        unsigned char c = m[i];
        if (c > 1) atomicOr(&weird, 1);
        if (c != 0 && (i & 3)) atomicOr(&off4, 1);
    }
    __syncthreads();
    if (threadIdx.x == 0) g_fmt = weird ? 2 : (off4 ? 1 : 0);
}
__global__ void convert_mask_kernel(const void* __restrict__ m) {
    int i = blockIdx.x * blockDim.x + threadIdx.x;
    if (i >= Nc) return;
    int fmt = g_fmt;
    unsigned char a;
    if (fmt == 0)      a = (((const int*)m)[i] != 0);
    else if (fmt == 1) a = (((const unsigned char*)m)[i] != 0);
    else               a = (((const float*)m)[i] != 0.0f);
    g_active[i] = a;
}
__global__ void binv_kernel(const float* __restrict__ beliefs) {
    int row = blockIdx.x * 8 + (threadIdx.x >> 5);
    int lane = threadIdx.x & 31;
    const float4* p = reinterpret_cast<const float4*>(beliefs + (size_t)row * Dc);
    float s = 0.0f;
    #pragma unroll
    for (int r = 0; r < 2; r++) {
        float4 v = p[lane + r * 32];
        s += v.x * v.x + v.y * v.y + v.z * v.z + v.w * v.w;
    }
    #pragma unroll
    for (int o = 16; o > 0; o >>= 1) s += __shfl_down_sync(0xffffffffu, s, o);
    if (lane == 0) g_binv[row] = 1.0f / fmaxf(sqrtf(s), EPSC);
}

// ============ gate/prec GEMM: single-term fp16, 4-stage pipeline ============
// block 128x128, 8 warps, K-chunk 32, stage = {A,B} @ 10240 B each = 20480 B.
#define GP_STG 20480
__global__ __launch_bounds__(256, 2) void gp_mma_kernel() {
    extern __shared__ __align__(128) char dsm[];
    __shared__ float s_b1[128], s_w2[128], s_red[128];

    const int tid = threadIdx.x, lane = tid & 31, wid = tid >> 5;
    const int bx = blockIdx.x;
    const int m0 = blockIdx.y * 128;
    const int nbase = bx * 128;
    const int warp_m = (wid >> 1) * 32;
    const int warp_n = (wid & 1) * 64;
    const uint32_t sbase = smem_u32(dsm);

    if (tid < 128) {
        s_b1[tid] = g_bc1[nbase + tid];
        s_w2[tid] = g_wc2[nbase + tid];
        s_red[tid] = 0.0f;
    }

    const int r = tid >> 1, seg = tid & 1;
    const char* pA = (const char*)(g_Af + (size_t)(m0 + r) * Hc + seg * 16);
    const char* pB = (const char*)(g_Wcf + (size_t)(nbase + r) * Hc + seg * 16);
    const uint32_t dOff = (uint32_t)r * 80 + (uint32_t)seg * 32;

    const uint32_t offA = (uint32_t)(warp_m + (lane & 15)) * 80 + (uint32_t)(lane >> 4) * 16;
    const uint32_t offB = (uint32_t)(warp_n + ((lane >> 4) << 3) + (lane & 7)) * 80
                        + (uint32_t)((lane >> 3) & 1) * 16;

    float acc[2][8][4];
    #pragma unroll
    for (int i = 0; i < 2; i++)
        #pragma unroll
        for (int j = 0; j < 8; j++)
            #pragma unroll
            for (int k = 0; k < 4; k++) acc[i][j][k] = 0.0f;

    // prologue: chunks 0..2
    #pragma unroll
    for (int c = 0; c < 3; c++) {
        const size_t kb = (size_t)c * 64;
        const uint32_t st = sbase + c * GP_STG + dOff;
        CP16(st,         pA + kb); CP16(st + 16,         pA + kb + 16);
        CP16(st + 10240, pB + kb); CP16(st + 10240 + 16, pB + kb + 16);
        CP_COMMIT();
    }

    for (int c = 0; c < 64; c++) {
        CP_WAIT2();
        __syncthreads();
        if (c + 3 < 64) {
            const size_t kb = (size_t)(c + 3) * 64;
            const uint32_t st = sbase + ((c + 3) & 3) * GP_STG + dOff;
            CP16(st,         pA + kb); CP16(st + 16,         pA + kb + 16);
            CP16(st + 10240, pB + kb); CP16(st + 10240 + 16, pB + kb + 16);
        }
        CP_COMMIT();
        const uint32_t uS = sbase + (c & 3) * GP_STG;
        const uint32_t uA = uS, uB = uS + 10240;
        #pragma unroll
        for (int ks = 0; ks < 2; ks++) {
            uint32_t a[2][4];
            LDSM4(a[0][0], a[0][1], a[0][2], a[0][3], uA + offA + ks * 32);
            LDSM4(a[1][0], a[1][1], a[1][2], a[1][3], uA + offA + 1280 + ks * 32);
            uint32_t b[8][2];
            #pragma unroll
            for (int jp = 0; jp < 4; jp++) {
                LDSM4(b[2*jp][0], b[2*jp][1], b[2*jp+1][0], b[2*jp+1][1],
                      uB + offB + (uint32_t)jp * 1280 + ks * 32);
            }
            #pragma unroll
            for (int mt = 0; mt < 2; mt++)
                #pragma unroll
                for (int nj = 0; nj < 8; nj++)
                    MMA_F16(acc[mt][nj], a[mt], b[nj]);
        }
    }
    __syncthreads();

    // fused relu + rank-1 epilogue
    const int qr = lane >> 2;
    const int qc = (lane & 3) * 2;
    #pragma unroll
    for (int mt = 0; mt < 2; mt++) {
        float p0 = 0.0f, p1 = 0.0f;
        #pragma unroll
        for (int nj = 0; nj < 8; nj++) {
            int col = warp_n + nj * 8 + qc;
            p0 += fmaxf(acc[mt][nj][0] + s_b1[col], 0.0f) * s_w2[col]
                + fmaxf(acc[mt][nj][1] + s_b1[col + 1], 0.0f) * s_w2[col + 1];
            p1 += fmaxf(acc[mt][nj][2] + s_b1[col], 0.0f) * s_w2[col]
                + fmaxf(acc[mt][nj][3] + s_b1[col + 1], 0.0f) * s_w2[col + 1];
        }
        p0 += __shfl_xor_sync(0xffffffffu, p0, 1);
        p0 += __shfl_xor_sync(0xffffffffu, p0, 2);
        p1 += __shfl_xor_sync(0xffffffffu, p1, 1);
        p1 += __shfl_xor_sync(0xffffffffu, p1, 2);
        if ((lane & 3) == 0) {
            atomicAdd(&s_red[warp_m + mt * 16 + qr], p0);
            atomicAdd(&s_red[warp_m + mt * 16 + 8 + qr], p1);
        }
    }
    __syncthreads();
    if (tid < 128) g_part[bx * MGP + m0 + tid] = s_red[tid];
}

// ============ obs GEMM: fp16 3-term split (hi/lo), 3-stage pipeline ============
#define OB_STG 40960
__global__ __launch_bounds__(256, 1) void obs_mma_kernel() {
    extern __shared__ __align__(128) char dsm[];

    const int tid = threadIdx.x, lane = tid & 31, wid = tid >> 5;
    const int m0 = blockIdx.y * 128;
    const int nbase = blockIdx.x * 128;
    const int warp_m = (wid >> 1) * 32;
    const int warp_n = (wid & 1) * 64;
    const uint32_t sbase = smem_u32(dsm);

    const int r = tid >> 1, seg = tid & 1;
    const char* pAh = (const char*)(g_Hmhi + (size_t)(m0 + r) * Hc + seg * 16);
    const char* pAl = (const char*)(g_Hmlo + (size_t)(m0 + r) * Hc + seg * 16);
    const char* pBh = (const char*)(g_Wohi + (size_t)(nbase + r) * Hc + seg * 16);
    const char* pBl = (const char*)(g_Wolo + (size_t)(nbase + r) * Hc + seg * 16);
    const uint32_t dOff = (uint32_t)r * 80 + (uint32_t)seg * 32;

    const uint32_t offA = (uint32_t)(warp_m + (lane & 15)) * 80 + (uint32_t)(lane >> 4) * 16;
    const uint32_t offB = (uint32_t)(warp_n + ((lane >> 4) << 3) + (lane & 7)) * 80
                        + (uint32_t)((lane >> 3) & 1) * 16;

    float acc[2][8][4];
    #pragma unroll
    for (int i = 0; i < 2; i++)
        #pragma unroll
        for (int j = 0; j < 8; j++)
            #pragma unroll
            for (int k = 0; k < 4; k++) acc[i][j][k] = 0.0f;

    #pragma unroll
    for (int c = 0; c < 2; c++) {
        const size_t kb = (size_t)c * 64;
        const uint32_t st = sbase + c * OB_STG + dOff;
        CP16(st,              pAh + kb); CP16(st + 16,             pAh + kb + 16);
        CP16(st + 10240,      pAl + kb); CP16(st + 10240 + 16,     pAl + kb + 16);
        CP16(st + 20480,      pBh + kb); CP16(st + 20480 + 16,     pBh + kb + 16);
        CP16(st + 30720,      pBl + kb); CP16(st + 30720 + 16,     pBl + kb + 16);
        CP_COMMIT();
    }

    for (int c = 0; c < 64; c++) {
        if (c + 2 < 64) {
            const size_t kb = (size_t)(c + 2) * 64;
            const uint32_t st = sbase + ((c + 2) % 3) * OB_STG + dOff;
            CP16(st,              pAh + kb); CP16(st + 16,             pAh + kb + 16);
            CP16(st + 10240,      pAl + kb); CP16(st + 10240 + 16,     pAl + kb + 16);
            CP16(st + 20480,      pBh + kb); CP16(st + 20480 + 16,     pBh + kb + 16);
            CP16(st + 30720,      pBl + kb); CP16(st + 30720 + 16,     pBl + kb + 16);
        }
        CP_COMMIT();
        CP_WAIT2();
        __syncthreads();
        const uint32_t uS = sbase + (c % 3) * OB_STG;
        const uint32_t uAh = uS, uAl = uS + 10240, uBh = uS + 20480, uBl = uS + 30720;
        #pragma unroll
        for (int ks = 0; ks < 2; ks++) {
            uint32_t ah[2][4], al[2][4];
            LDSM4(ah[0][0], ah[0][1], ah[0][2], ah[0][3], uAh + offA + ks * 32);
            LDSM4(ah[1][0], ah[1][1], ah[1][2], ah[1][3], uAh + offA + 1280 + ks * 32);
            LDSM4(al[0][0], al[0][1], al[0][2], al[0][3], uAl + offA + ks * 32);
            LDSM4(al[1][0], al[1][1], al[1][2], al[1][3], uAl + offA + 1280 + ks * 32);
            uint32_t bh[8][2], bl[8][2];
            #pragma unroll
            for (int jp = 0; jp < 4; jp++) {
                LDSM4(bh[2*jp][0], bh[2*jp][1], bh[2*jp+1][0], bh[2*jp+1][1],
                      uBh + offB + (uint32_t)jp * 1280 + ks * 32);
                LDSM4(bl[2*jp][0], bl[2*jp][1], bl[2*jp+1][0], bl[2*jp+1][1],
                      uBl + offB + (uint32_t)jp * 1280 + ks * 32);
            }
            #pragma unroll
            for (int mt = 0; mt < 2; mt++)
                #pragma unroll
                for (int nj = 0; nj < 8; nj++) {
                    MMA_F16(acc[mt][nj], ah[mt], bh[nj]);
                    MMA_F16(acc[mt][nj], ah[mt], bl[nj]);
                    MMA_F16(acc[mt][nj], al[mt], bh[nj]);
                }
        }
        __syncthreads();
    }

    const int qr = lane >> 2;
    const int qc = (lane & 3) * 2;
    #pragma unroll
    for (int mt = 0; mt < 2; mt++)
        #pragma unroll
        for (int nj = 0; nj < 8; nj++) {
            int row = m0 + warp_m + mt * 16 + qr;
            int col = nbase + warp_n + nj * 8 + qc;
            *(float2*)(g_obs_mean + (size_t)row * Dc + col) = make_float2(acc[mt][nj][0], acc[mt][nj][1]);
            *(float2*)(g_obs_mean + (size_t)(row + 8) * Dc + col) = make_float2(acc[mt][nj][2], acc[mt][nj][3]);
        }
}

// ============ sims GEMM: fp16, 4-stage pipeline + masked argmax ============
#define SM_STG 20480
__global__ __launch_bounds__(256, 2) void sims_mma_kernel() {
    extern __shared__ __align__(128) char dsm[];
    __shared__ float s_binv[128];
    __shared__ unsigned char s_act[128];

    const int tid = threadIdx.x, lane = tid & 31, wid = tid >> 5;
    const int n0 = blockIdx.x * 128;
    const int m0 = blockIdx.y * 128;
    const int warp_m = (wid >> 1) * 32;
    const int warp_n = (wid & 1) * 64;
    const uint32_t sbase = smem_u32(dsm);

    if (tid < 128) { s_binv[tid] = g_binv[n0 + tid]; s_act[tid] = g_active[n0 + tid]; }

    const int r = tid >> 1, seg = tid & 1;
    const char* pA = (const char*)(g_oangb + (size_t)(m0 + r) * Dc + seg * 16);
    const char* pB = (const char*)(g_Bb + (size_t)(n0 + r) * Dc + seg * 16);
    const uint32_t dOff = (uint32_t)r * 80 + (uint32_t)seg * 32;

    const uint32_t offA = (uint32_t)(warp_m + (lane & 15)) * 80 + (uint32_t)(lane >> 4) * 16;
    const uint32_t offB = (uint32_t)(warp_n + ((lane >> 4) << 3) + (lane & 7)) * 80
                        + (uint32_t)((lane >> 3) & 1) * 16;

    float acc[2][8][4];
    #pragma unroll
    for (int i = 0; i < 2; i++)
        #pragma unroll
        for (int j = 0; j < 8; j++)
            #pragma unroll
            for (int k = 0; k < 4; k++) acc[i][j][k] = 0.0f;

    #pragma unroll
    for (int c = 0; c < 3; c++) {
        const size_t kb = (size_t)c * 64;
        const uint32_t st = sbase + c * SM_STG + dOff;
        CP16(st,         pA + kb); CP16(st + 16,         pA + kb + 16);
        CP16(st + 10240, pB + kb); CP16(st + 10240 + 16, pB + kb + 16);
        CP_COMMIT();
    }

    for (int c = 0; c < 8; c++) {
        CP_WAIT2();
        __syncthreads();
        if (c + 3 < 8) {
            const size_t kb = (size_t)(c + 3) * 64;
            const uint32_t st = sbase + ((c + 3) & 3) * SM_STG + dOff;
            CP16(st,         pA + kb); CP16(st + 16,         pA + kb + 16);
            CP16(st + 10240, pB + kb); CP16(st + 10240 + 16, pB + kb + 16);
        }
        CP_COMMIT();
        const uint32_t uS = sbase + (c & 3) * SM_STG;
        const uint32_t uA = uS, uB = uS + 10240;
        #pragma unroll
        for (int ks = 0; ks < 2; ks++) {
            uint32_t a[2][4];
            LDSM4(a[0][0], a[0][1], a[0][2], a[0][3], uA + offA + ks * 32);
            LDSM4(a[1][0], a[1][1], a[1][2], a[1][3], uA + offA + 1280 + ks * 32);
            uint32_t b[8][2];
            #pragma unroll
            for (int jp = 0; jp < 4; jp++) {
                LDSM4(b[2*jp][0], b[2*jp][1], b[2*jp+1][0], b[2*jp+1][1],
                      uB + offB + (uint32_t)jp * 1280 + ks * 32);
            }
            #pragma unroll
            for (int mt = 0; mt < 2; mt++)
                #pragma unroll
                for (int nj = 0; nj < 8; nj++)
                    MMA_F16(acc[mt][nj], a[mt], b[nj]);
        }
    }

    const int qr = lane >> 2;
    const int qc = (lane & 3) * 2;
    #pragma unroll
    for (int mt = 0; mt < 2; mt++) {
        unsigned long long b0 = 0ULL, b1 = 0ULL;
        #pragma unroll
        for (int nj = 0; nj < 8; nj++) {
            int ln = warp_n + nj * 8 + qc;
            #pragma unroll
            for (int p = 0; p < 2; p++) {
                int l = ln + p;
                if (s_act[l]) {
                    unsigned long long key2 = 0xFFFFFFFFu - (unsigned)(n0 + l);
                    float s0 = acc[mt][nj][p] * s_binv[l];
                    unsigned long long q0 = ((unsigned long long)enc_f(s0) << 32) | key2;
                    if (q0 > b0) b0 = q0;
                    float s1 = acc[mt][nj][2 + p] * s_binv[l];
                    unsigned long long q1 = ((unsigned long long)enc_f(s1) << 32) | key2;
                    if (q1 > b1) b1 = q1;
                }
            }
        }
        unsigned long long t;
        t = __shfl_xor_sync(0xffffffffu, b0, 1); if (t > b0) b0 = t;
        t = __shfl_xor_sync(0xffffffffu, b0, 2); if (t > b0) b0 = t;
        t = __shfl_xor_sync(0xffffffffu, b1, 1); if (t > b1) b1 = t;
        t = __shfl_xor_sync(0xffffffffu, b1, 2); if (t > b1) b1 = t;
        if ((lane & 3) == 0) {
            if (b0) atomicMax(&g_best[m0 + warp_m + mt * 16 + qr], b0);
            if (b1) atomicMax(&g_best[m0 + warp_m + mt * 16 + 8 + qr], b1);
        }
    }
}

// ---------------- finalize ----------------
__global__ __launch_bounds__(256) void finalize1_kernel(
    const float* __restrict__ bg2, const float* __restrict__ bp2,
    float* __restrict__ out_obs, float* __restrict__ out_meaning, int write_extra)
{
    __shared__ float sred[256];
    __shared__ float s_pm, s_inv, s_rinv;
    int t = blockIdx.x;
    int d = threadIdx.x;
    float v = g_obs_mean[(size_t)t * Dc + d];

    sred[d] = v * v;
    __syncthreads();
    for (int s = 128; s > 0; s >>= 1) {
        if (d < s) sred[d] += sred[d + s];
        __syncthreads();
    }
    if (d == 0) {
        float pm = 0.0f;
        float bg2v = bg2[0], bp2v = bp2[0];
        #pragma unroll
        for (int b = 0; b < Bc; b++) {
            int row = b * Tc + t;
            float gl = bg2v, pl = bp2v;
            #pragma unroll
            for (int jt = 0; jt < 4; jt++) gl += g_part[jt * MGP + row];
            #pragma unroll
            for (int jt = 4; jt < 8; jt++) pl += g_part[jt * MGP + row];
            pm += sigmoidf_(gl) * softplusf_(pl);
        }
        pm *= 0.25f;
        s_pm = pm;
        s_inv = 1.0f / fmaxf(sqrtf(sred[0]), EPSC);
    }
    __syncthreads();
    float ob = v * s_inv * s_pm;
    out_obs[(size_t)t * Dc + d] = ob;

    __syncthreads();
    sred[d] = ob * ob;
    __syncthreads();
    for (int s = 128; s > 0; s >>= 1) {
        if (d < s) sred[d] += sred[d + s];
        __syncthreads();
    }
    if (d == 0) {
        float rr = sqrtf(sred[0]);
        g_rad[t] = rr;
        s_rinv = 1.0f / fmaxf(rr, EPSC);
        if (write_extra) out_meaning[t] = (rr > 0.05f) ? 1.0f : 0.0f;
    }
    __syncthreads();
    g_oangb[(size_t)t * Dc + d] = __float2half_rn(ob * s_rinv);
}

__global__ void init_best_kernel() {
    int i = blockIdx.x * blockDim.x + threadIdx.x;
    if (i < Tc) g_best[i] = 0ULL;
}

__global__ void finalize2_kernel(float* __restrict__ out_sims, float* __restrict__ out_slots) {
    int t = blockIdx.x * blockDim.x + threadIdx.x;
    if (t >= Tc) return;
    unsigned long long b = g_best[t];
    float sim = 0.0f;
    int idx = -1;
    bool has = (b != 0ULL);
    if (has) {
        sim = dec_f((unsigned)(b >> 32));
        idx = (int)(0xFFFFFFFFu - (unsigned)(b & 0xFFFFFFFFu));
    }
    bool matched = has && (g_rad[t] > 0.05f) && (sim > 0.5f);
    out_sims[t]  = matched ? sim : 0.0f;
    out_slots[t] = matched ? (float)idx : -1.0f;
}

// ---------------- launcher ----------------
extern "C" void kernel_launch(void* const* d_in, const int* in_sizes, int n_in,
                              void* d_out, int out_size)
{
    const float* hidden  = (const float*)d_in[0];
    const float* beliefs = (const float*)d_in[1];
    const void*  maskp   = d_in[2];
    const float* W_obs   = (const float*)d_in[3];
    const float* W_g1    = (const float*)d_in[4];
    const float* b_g1    = (const float*)d_in[5];
    const float* W_g2    = (const float*)d_in[6];
    const float* b_g2    = (const float*)d_in[7];
    const float* W_p1    = (const float*)d_in[8];
    const float* b_p1    = (const float*)d_in[9];
    const float* W_p2    = (const float*)d_in[10];
    const float* b_p2    = (const float*)d_in[11];
    float* out = (float*)d_out;

    static int attr_set = 0;
    if (!attr_set) {
        cudaFuncSetAttribute(gp_mma_kernel, cudaFuncAttributeMaxDynamicSharedMemorySize, 4 * GP_STG);
        cudaFuncSetAttribute(obs_mma_kernel, cudaFuncAttributeMaxDynamicSharedMemorySize, 3 * OB_STG);
        cudaFuncSetAttribute(sims_mma_kernel, cudaFuncAttributeMaxDynamicSharedMemorySize, 4 * SM_STG);
        attr_set = 1;
    }

    const size_t base = (size_t)Tc * Dc;
    const int write_extra = (out_size >= (int)(base + 3 * Tc)) ? 1 : 0;
    float* out_obs     = out;
    float* out_sims    = out + base;
    float* out_slots   = out + base + Tc;
    float* out_meaning = out + base + 2 * Tc;

    prep_hidden_kernel<<<(Tc * 512) / 256, 256>>>(hidden);
    prep_weights_kernel<<<(1280 * 512) / 256, 256>>>(W_g1, W_p1, W_obs);
    prep_small_kernel<<<4, 256>>>(b_g1, b_p1, W_g2, W_p2);
    prep_beliefs_kernel<<<((size_t)Nc * Dc / 4) / 256, 256>>>(beliefs);
    detect_mask_kernel<<<1, 256>>>((const unsigned char*)maskp, Nc);
    convert_mask_kernel<<<Nc / 256, 256>>>(maskp);
    binv_kernel<<<Nc / 8, 256>>>(beliefs);
    init_best_kernel<<<Tc / 256, 256>>>();

    gp_mma_kernel<<<dim3(8, MGP / 128), 256, 4 * GP_STG>>>();
    obs_mma_kernel<<<dim3(2, Tc / 128), 256, 3 * OB_STG>>>();
    finalize1_kernel<<<Tc, 256>>>(b_g2, b_p2, out_obs, out_meaning, write_extra);

    sims_mma_kernel<<<dim3(Nc / 128, Tc / 128), 256, 4 * SM_STG>>>();
    if (write_extra) {
        finalize2_kernel<<<Tc / 256, 256>>>(out_sims, out_slots);
    }
}

// round 6
// speedup vs baseline: 5.3849x; 1.0241x over previous
#include <cuda_runtime.h>
#include <cuda_fp16.h>
#include <cstdint>

#define Bc 4
#define Tc 4096
#define Hc 2048
#define Dc 256
#define Nc 32768
#define MGP (Bc*Tc)
#define EPSC 1e-8f

// ---------------- device scratch ----------------
__device__ __half g_Af[(size_t)MGP * Hc];        // hidden, fp16
__device__ __half g_Hmhi[(size_t)Tc * Hc];       // batch-mean hidden hi/lo
__device__ __half g_Hmlo[(size_t)Tc * Hc];
__device__ __half g_Wcf[(size_t)1024 * Hc];      // gate+prec W1, fp16
__device__ __half g_Wohi[(size_t)Dc * Hc];       // W_obs hi/lo
__device__ __half g_Wolo[(size_t)Dc * Hc];
__device__ unsigned char g_Bb8[(size_t)Nc * Dc];   // beliefs e4m3 (x16)
__device__ unsigned char g_oang8[(size_t)Tc * Dc]; // o_angles e4m3 (x16)
__device__ float g_bc1[1024];
__device__ float g_wc2[1024];
__device__ float g_obs_mean[(size_t)Tc * Dc];
__device__ float g_part[8 * MGP];
__device__ float g_binv[Nc];                     // 1/(256*clip(norm,eps))
__device__ unsigned char g_active[Nc];
__device__ unsigned long long g_best[Tc];
__device__ float g_rad[Tc];
__device__ int g_fmt;

// ---------------- helpers ----------------
__device__ __forceinline__ uint32_t smem_u32(const void* p) {
    uint32_t a;
    asm("{ .reg .u64 t; cvta.to.shared.u64 t, %1; cvt.u32.u64 %0, t; }" : "=r"(a) : "l"(p));
    return a;
}
#define LDSM4(R0, R1, R2, R3, A) \
    asm volatile("ldmatrix.sync.aligned.m8n8.x4.shared.b16 {%0,%1,%2,%3}, [%4];" \
        : "=r"(R0), "=r"(R1), "=r"(R2), "=r"(R3) : "r"(A))
#define MMA_F16(D, A, B) \
    asm volatile("mma.sync.aligned.m16n8k16.row.col.f32.f16.f16.f32 " \
        "{%0,%1,%2,%3}, {%4,%5,%6,%7}, {%8,%9}, {%0,%1,%2,%3};" \
        : "+f"((D)[0]), "+f"((D)[1]), "+f"((D)[2]), "+f"((D)[3]) \
        : "r"((A)[0]), "r"((A)[1]), "r"((A)[2]), "r"((A)[3]), "r"((B)[0]), "r"((B)[1]))
#define MMA_F8(D, A, B) \
    asm volatile("mma.sync.aligned.m16n8k32.row.col.f32.e4m3.e4m3.f32 " \
        "{%0,%1,%2,%3}, {%4,%5,%6,%7}, {%8,%9}, {%0,%1,%2,%3};" \
        : "+f"((D)[0]), "+f"((D)[1]), "+f"((D)[2]), "+f"((D)[3]) \
        : "r"((A)[0]), "r"((A)[1]), "r"((A)[2]), "r"((A)[3]), "r"((B)[0]), "r"((B)[1]))
#define CP16(DST, SRC) \
    asm volatile("cp.async.cg.shared.global [%0], [%1], 16;" :: "r"(DST), "l"(SRC) : "memory")
#define CP_COMMIT() asm volatile("cp.async.commit_group;" ::: "memory")
#define CP_WAIT1()  asm volatile("cp.async.wait_group 1;" ::: "memory")
#define CP_WAIT2()  asm volatile("cp.async.wait_group 2;" ::: "memory")

__device__ __forceinline__ unsigned enc_f(float f) {
    unsigned u = __float_as_uint(f);
    return (u & 0x80000000u) ? ~u : (u | 0x80000000u);
}
__device__ __forceinline__ float dec_f(unsigned e) {
    unsigned u = (e & 0x80000000u) ? (e ^ 0x80000000u) : ~e;
    return __uint_as_float(u);
}
__device__ __forceinline__ float sigmoidf_(float x) { return 1.0f / (1.0f + expf(-x)); }
__device__ __forceinline__ float softplusf_(float x) {
    return fmaxf(x, 0.0f) + log1pf(expf(-fabsf(x)));
}
__device__ __forceinline__ uint16_t pack_e4m3(float lo, float hi) {
    uint16_t r;
    asm("cvt.rn.satfinite.e4m3x2.f32 %0, %1, %2;" : "=h"(r) : "f"(hi), "f"(lo));
    return r;
}
__device__ __forceinline__ void split_store_h(__half* hi, __half* lo, float4 v) {
    __half h0 = __float2half_rn(v.x);
    __half h1 = __float2half_rn(v.y);
    __half h2 = __float2half_rn(v.z);
    __half h3 = __float2half_rn(v.w);
    __half l0 = __float2half_rn(v.x - __half2float(h0));
    __half l1 = __float2half_rn(v.y - __half2float(h1));
    __half l2 = __float2half_rn(v.z - __half2float(h2));
    __half l3 = __float2half_rn(v.w - __half2float(h3));
    ((__half2*)hi)[0] = __halves2half2(h0, h1);
    ((__half2*)hi)[1] = __halves2half2(h2, h3);
    ((__half2*)lo)[0] = __halves2half2(l0, l1);
    ((__half2*)lo)[1] = __halves2half2(l2, l3);
}
__device__ __forceinline__ void h_store4(__half* dst, float4 v) {
    ((__half2*)dst)[0] = __halves2half2(__float2half_rn(v.x), __float2half_rn(v.y));
    ((__half2*)dst)[1] = __halves2half2(__float2half_rn(v.z), __float2half_rn(v.w));
}

// ---------------- prep kernels ----------------
__global__ void prep_hidden_kernel(const float* __restrict__ hidden) {
    int idx = blockIdx.x * blockDim.x + threadIdx.x;
    int t = idx >> 9, h = (idx & 511) * 4;
    float4 acc = make_float4(0, 0, 0, 0);
    #pragma unroll
    for (int b = 0; b < Bc; b++) {
        size_t row = (size_t)(b * Tc + t);
        float4 v = *(const float4*)(hidden + row * Hc + h);
        h_store4(g_Af + row * Hc + h, v);
        acc.x += v.x; acc.y += v.y; acc.z += v.z; acc.w += v.w;
    }
    acc.x *= 0.25f; acc.y *= 0.25f; acc.z *= 0.25f; acc.w *= 0.25f;
    split_store_h(g_Hmhi + (size_t)t * Hc + h, g_Hmlo + (size_t)t * Hc + h, acc);
}

__global__ void prep_weights_kernel(const float* __restrict__ Wg1, const float* __restrict__ Wp1,
                                    const float* __restrict__ Wobs) {
    int idx = blockIdx.x * blockDim.x + threadIdx.x;
    int row = idx >> 9, h = (idx & 511) * 4;
    if (row < 1024) {
        const float* src = (row < 512) ? (Wg1 + (size_t)row * Hc) : (Wp1 + (size_t)(row - 512) * Hc);
        float4 v = *(const float4*)(src + h);
        h_store4(g_Wcf + (size_t)row * Hc + h, v);
    } else {
        int r2 = row - 1024;
        float4 v = *(const float4*)(Wobs + (size_t)r2 * Hc + h);
        split_store_h(g_Wohi + (size_t)r2 * Hc + h, g_Wolo + (size_t)r2 * Hc + h, v);
    }
}

__global__ void prep_small_kernel(const float* __restrict__ bg1, const float* __restrict__ bp1,
                                  const float* __restrict__ Wg2, const float* __restrict__ Wp2) {
    int i = blockIdx.x * blockDim.x + threadIdx.x;
    if (i < 1024) {
        g_bc1[i] = (i < 512) ? bg1[i] : bp1[i - 512];
        g_wc2[i] = (i < 512) ? Wg2[i] : Wp2[i - 512];
    }
}

__global__ void prep_beliefs_kernel(const float* __restrict__ beliefs) {
    int idx = blockIdx.x * blockDim.x + threadIdx.x;   // Nc*Dc/4 threads
    size_t e = (size_t)idx * 4;
    float4 v = *(const float4*)(beliefs + e);
    uint16_t lo = pack_e4m3(v.x * 16.0f, v.y * 16.0f);
    uint16_t hi = pack_e4m3(v.z * 16.0f, v.w * 16.0f);
    *(uint32_t*)(g_Bb8 + e) = ((uint32_t)hi << 16) | lo;
}

__global__ void detect_mask_kernel(const unsigned char* __restrict__ m, int nbytes) {
    __shared__ int weird, off4;
    if (threadIdx.x == 0) { weird = 0; off4 = 0; }
    __syncthreads();
    for (int i = threadIdx.x; i < nbytes; i += blockDim.x) {
        unsigned char c = m[i];
        if (c > 1) atomicOr(&weird, 1);
        if (c != 0 && (i & 3)) atomicOr(&off4, 1);
    }
    __syncthreads();
    if (threadIdx.x == 0) g_fmt = weird ? 2 : (off4 ? 1 : 0);
}
__global__ void convert_mask_kernel(const void* __restrict__ m) {
    int i = blockIdx.x * blockDim.x + threadIdx.x;
    if (i >= Nc) return;
    int fmt = g_fmt;
    unsigned char a;
    if (fmt == 0)      a = (((const int*)m)[i] != 0);
    else if (fmt == 1) a = (((const unsigned char*)m)[i] != 0);
    else               a = (((const float*)m)[i] != 0.0f);
    g_active[i] = a;
}
__global__ void binv_kernel(const float* __restrict__ beliefs) {
    int row = blockIdx.x * 8 + (threadIdx.x >> 5);
    int lane = threadIdx.x & 31;
    const float4* p = reinterpret_cast<const float4*>(beliefs + (size_t)row * Dc);
    float s = 0.0f;
    #pragma unroll
    for (int r = 0; r < 2; r++) {
        float4 v = p[lane + r * 32];
        s += v.x * v.x + v.y * v.y + v.z * v.z + v.w * v.w;
    }
    #pragma unroll
    for (int o = 16; o > 0; o >>= 1) s += __shfl_down_sync(0xffffffffu, s, o);
    // folds 1/256 for the x16-scaled e4m3 operands in the sims GEMM
    if (lane == 0) g_binv[row] = 1.0f / (256.0f * fmaxf(sqrtf(s), EPSC));
}

// ============ merged gate/prec + obs GEMM kernel ============
// blockIdx.x < 8  : gp path, fp16 single-term, 4-stage pipe, CTA 128x128
// blockIdx.x == 8 : obs path (blockIdx.y<64), fp16 3-term hi/lo, 2-stage pipe
#define GP_STG 20480
#define OB_STG 40960
#define DYN_SMEM 81920

__global__ __launch_bounds__(256, 2) void gpobs_mma_kernel() {
    extern __shared__ __align__(128) char dsm[];
    __shared__ float s_b1[128], s_w2[128], s_red[128];

    const int tid = threadIdx.x, lane = tid & 31, wid = tid >> 5;
    const int warp_m = (wid >> 1) * 32;
    const int warp_n = (wid & 1) * 64;
    const uint32_t sbase = smem_u32(dsm);
    const int r = tid >> 1, seg = tid & 1;
    const uint32_t dOff = (uint32_t)r * 80 + (uint32_t)seg * 32;
    const uint32_t offA = (uint32_t)(warp_m + (lane & 15)) * 80 + (uint32_t)(lane >> 4) * 16;
    const uint32_t offB = (uint32_t)(warp_n + ((lane >> 4) << 3) + (lane & 7)) * 80
                        + (uint32_t)((lane >> 3) & 1) * 16;

    float acc[2][8][4];
    #pragma unroll
    for (int i = 0; i < 2; i++)
        #pragma unroll
        for (int j = 0; j < 8; j++)
            #pragma unroll
            for (int k = 0; k < 4; k++) acc[i][j][k] = 0.0f;

    const int qr = lane >> 2;
    const int qc = (lane & 3) * 2;

    if (blockIdx.x < 8) {
        // ---------------- gate/prec path ----------------
        const int bx = blockIdx.x;
        const int m0 = blockIdx.y * 128;
        const int nbase = bx * 128;
        if (tid < 128) {
            s_b1[tid] = g_bc1[nbase + tid];
            s_w2[tid] = g_wc2[nbase + tid];
            s_red[tid] = 0.0f;
        }
        const char* pA = (const char*)(g_Af + (size_t)(m0 + r) * Hc + seg * 16);
        const char* pB = (const char*)(g_Wcf + (size_t)(nbase + r) * Hc + seg * 16);

        #pragma unroll
        for (int c = 0; c < 3; c++) {
            const size_t kb = (size_t)c * 64;
            const uint32_t st = sbase + c * GP_STG + dOff;
            CP16(st,         pA + kb); CP16(st + 16,         pA + kb + 16);
            CP16(st + 10240, pB + kb); CP16(st + 10240 + 16, pB + kb + 16);
            CP_COMMIT();
        }

        for (int c = 0; c < 64; c++) {
            CP_WAIT2();
            __syncthreads();
            if (c + 3 < 64) {
                const size_t kb = (size_t)(c + 3) * 64;
                const uint32_t st = sbase + ((c + 3) & 3) * GP_STG + dOff;
                CP16(st,         pA + kb); CP16(st + 16,         pA + kb + 16);
                CP16(st + 10240, pB + kb); CP16(st + 10240 + 16, pB + kb + 16);
            }
            CP_COMMIT();
            const uint32_t uS = sbase + (c & 3) * GP_STG;
            const uint32_t uA = uS, uB = uS + 10240;
            #pragma unroll
            for (int ks = 0; ks < 2; ks++) {
                uint32_t a[2][4];
                LDSM4(a[0][0], a[0][1], a[0][2], a[0][3], uA + offA + ks * 32);
                LDSM4(a[1][0], a[1][1], a[1][2], a[1][3], uA + offA + 1280 + ks * 32);
                uint32_t b[8][2];
                #pragma unroll
                for (int jp = 0; jp < 4; jp++) {
                    LDSM4(b[2*jp][0], b[2*jp][1], b[2*jp+1][0], b[2*jp+1][1],
                          uB + offB + (uint32_t)jp * 1280 + ks * 32);
                }
                #pragma unroll
                for (int mt = 0; mt < 2; mt++)
                    #pragma unroll
                    for (int nj = 0; nj < 8; nj++)
                        MMA_F16(acc[mt][nj], a[mt], b[nj]);
            }
        }
        __syncthreads();

        #pragma unroll
        for (int mt = 0; mt < 2; mt++) {
            float p0 = 0.0f, p1 = 0.0f;
            #pragma unroll
            for (int nj = 0; nj < 8; nj++) {
                int col = warp_n + nj * 8 + qc;
                p0 += fmaxf(acc[mt][nj][0] + s_b1[col], 0.0f) * s_w2[col]
                    + fmaxf(acc[mt][nj][1] + s_b1[col + 1], 0.0f) * s_w2[col + 1];
                p1 += fmaxf(acc[mt][nj][2] + s_b1[col], 0.0f) * s_w2[col]
                    + fmaxf(acc[mt][nj][3] + s_b1[col + 1], 0.0f) * s_w2[col + 1];
            }
            p0 += __shfl_xor_sync(0xffffffffu, p0, 1);
            p0 += __shfl_xor_sync(0xffffffffu, p0, 2);
            p1 += __shfl_xor_sync(0xffffffffu, p1, 1);
            p1 += __shfl_xor_sync(0xffffffffu, p1, 2);
            if ((lane & 3) == 0) {
                atomicAdd(&s_red[warp_m + mt * 16 + qr], p0);
                atomicAdd(&s_red[warp_m + mt * 16 + 8 + qr], p1);
            }
        }
        __syncthreads();
        if (tid < 128) g_part[bx * MGP + m0 + tid] = s_red[tid];
    } else {
        // ---------------- obs path (3-term fp16 hi/lo, 2-stage) ----------------
        const int id = blockIdx.y;
        if (id >= 64) return;
        const int nbase = (id & 1) * 128;
        const int m0 = (id >> 1) * 128;

        const char* pAh = (const char*)(g_Hmhi + (size_t)(m0 + r) * Hc + seg * 16);
        const char* pAl = (const char*)(g_Hmlo + (size_t)(m0 + r) * Hc + seg * 16);
        const char* pBh = (const char*)(g_Wohi + (size_t)(nbase + r) * Hc + seg * 16);
        const char* pBl = (const char*)(g_Wolo + (size_t)(nbase + r) * Hc + seg * 16);

        {
            const uint32_t st = sbase + dOff;
            CP16(st,         pAh); CP16(st + 16,         pAh + 16);
            CP16(st + 10240, pAl); CP16(st + 10240 + 16, pAl + 16);
            CP16(st + 20480, pBh); CP16(st + 20480 + 16, pBh + 16);
            CP16(st + 30720, pBl); CP16(st + 30720 + 16, pBl + 16);
            CP_COMMIT();
        }

        for (int c = 0; c < 64; c++) {
            if (c + 1 < 64) {
                const size_t kb = (size_t)(c + 1) * 64;
                const uint32_t st = sbase + ((c + 1) & 1) * OB_STG + dOff;
                CP16(st,         pAh + kb); CP16(st + 16,         pAh + kb + 16);
                CP16(st + 10240, pAl + kb); CP16(st + 10240 + 16, pAl + kb + 16);
                CP16(st + 20480, pBh + kb); CP16(st + 20480 + 16, pBh + kb + 16);
                CP16(st + 30720, pBl + kb); CP16(st + 30720 + 16, pBl + kb + 16);
            }
            CP_COMMIT();
            CP_WAIT1();
            __syncthreads();
            const uint32_t uS = sbase + (c & 1) * OB_STG;
            const uint32_t srcA[3] = {uS, uS, uS + 10240};
            const uint32_t srcB[3] = {uS + 20480, uS + 30720, uS + 20480};
            #pragma unroll
            for (int tr = 0; tr < 3; tr++) {
                #pragma unroll
                for (int ks = 0; ks < 2; ks++) {
                    uint32_t a[2][4];
                    LDSM4(a[0][0], a[0][1], a[0][2], a[0][3], srcA[tr] + offA + ks * 32);
                    LDSM4(a[1][0], a[1][1], a[1][2], a[1][3], srcA[tr] + offA + 1280 + ks * 32);
                    uint32_t b[8][2];
                    #pragma unroll
                    for (int jp = 0; jp < 4; jp++) {
                        LDSM4(b[2*jp][0], b[2*jp][1], b[2*jp+1][0], b[2*jp+1][1],
                              srcB[tr] + offB + (uint32_t)jp * 1280 + ks * 32);
                    }
                    #pragma unroll
                    for (int mt = 0; mt < 2; mt++)
                        #pragma unroll
                        for (int nj = 0; nj < 8; nj++)
                            MMA_F16(acc[mt][nj], a[mt], b[nj]);
                }
            }
            __syncthreads();
        }

        #pragma unroll
        for (int mt = 0; mt < 2; mt++)
            #pragma unroll
            for (int nj = 0; nj < 8; nj++) {
                int row = m0 + warp_m + mt * 16 + qr;
                int col = nbase + warp_n + nj * 8 + qc;
                *(float2*)(g_obs_mean + (size_t)row * Dc + col) = make_float2(acc[mt][nj][0], acc[mt][nj][1]);
                *(float2*)(g_obs_mean + (size_t)(row + 8) * Dc + col) = make_float2(acc[mt][nj][2], acc[mt][nj][3]);
            }
    }
}

// ============ sims GEMM: fp8 e4m3, 4-stage pipeline + masked argmax ============
#define SM_STG 20480
__global__ __launch_bounds__(256, 2) void sims_mma_kernel() {
    extern __shared__ __align__(128) char dsm[];
    __shared__ float s_binv[128];
    __shared__ unsigned char s_act[128];

    const int tid = threadIdx.x, lane = tid & 31, wid = tid >> 5;
    const int n0 = blockIdx.x * 128;
    const int m0 = blockIdx.y * 128;
    const int warp_m = (wid >> 1) * 32;
    const int warp_n = (wid & 1) * 64;
    const uint32_t sbase = smem_u32(dsm);

    if (tid < 128) { s_binv[tid] = g_binv[n0 + tid]; s_act[tid] = g_active[n0 + tid]; }

    const int r = tid >> 1, seg = tid & 1;
    const char* pA = (const char*)(g_oang8 + (size_t)(m0 + r) * Dc + seg * 32);
    const char* pB = (const char*)(g_Bb8 + (size_t)(n0 + r) * Dc + seg * 32);
    const uint32_t dOff = (uint32_t)r * 80 + (uint32_t)seg * 32;

    const uint32_t offA = (uint32_t)(warp_m + (lane & 15)) * 80 + (uint32_t)(lane >> 4) * 16;
    const uint32_t offB = (uint32_t)(warp_n + ((lane >> 4) << 3) + (lane & 7)) * 80
                        + (uint32_t)((lane >> 3) & 1) * 16;

    float acc[2][8][4];
    #pragma unroll
    for (int i = 0; i < 2; i++)
        #pragma unroll
        for (int j = 0; j < 8; j++)
            #pragma unroll
            for (int k = 0; k < 4; k++) acc[i][j][k] = 0.0f;

    // 4 chunks of 64 fp8 (64 bytes per row per chunk)
    #pragma unroll
    for (int c = 0; c < 3; c++) {
        const size_t kb = (size_t)c * 64;
        const uint32_t st = sbase + c * SM_STG + dOff;
        CP16(st,         pA + kb); CP16(st + 16,         pA + kb + 16);
        CP16(st + 10240, pB + kb); CP16(st + 10240 + 16, pB + kb + 16);
        CP_COMMIT();
    }

    for (int c = 0; c < 4; c++) {
        CP_WAIT2();
        __syncthreads();
        if (c + 3 < 4) {
            const size_t kb = (size_t)(c + 3) * 64;
            const uint32_t st = sbase + ((c + 3) & 3) * SM_STG + dOff;
            CP16(st,         pA + kb); CP16(st + 16,         pA + kb + 16);
            CP16(st + 10240, pB + kb); CP16(st + 10240 + 16, pB + kb + 16);
        }
        CP_COMMIT();
        const uint32_t uS = sbase + (c & 3) * SM_STG;
        const uint32_t uA = uS, uB = uS + 10240;
        #pragma unroll
        for (int ks = 0; ks < 2; ks++) {        // two k32 steps (32 bytes each)
            uint32_t a[2][4];
            LDSM4(a[0][0], a[0][1], a[0][2], a[0][3], uA + offA + ks * 32);
            LDSM4(a[1][0], a[1][1], a[1][2], a[1][3], uA + offA + 1280 + ks * 32);
            uint32_t b[8][2];
            #pragma unroll
            for (int jp = 0; jp < 4; jp++) {
                LDSM4(b[2*jp][0], b[2*jp][1], b[2*jp+1][0], b[2*jp+1][1],
                      uB + offB + (uint32_t)jp * 1280 + ks * 32);
            }
            #pragma unroll
            for (int mt = 0; mt < 2; mt++)
                #pragma unroll
                for (int nj = 0; nj < 8; nj++)
                    MMA_F8(acc[mt][nj], a[mt], b[nj]);
        }
    }

    const int qr = lane >> 2;
    const int qc = (lane & 3) * 2;
    #pragma unroll
    for (int mt = 0; mt < 2; mt++) {
        unsigned long long b0 = 0ULL, b1 = 0ULL;
        #pragma unroll
        for (int nj = 0; nj < 8; nj++) {
            int ln = warp_n + nj * 8 + qc;
            #pragma unroll
            for (int p = 0; p < 2; p++) {
                int l = ln + p;
                if (s_act[l]) {
                    unsigned long long key2 = 0xFFFFFFFFu - (unsigned)(n0 + l);
                    float s0 = acc[mt][nj][p] * s_binv[l];
                    unsigned long long q0 = ((unsigned long long)enc_f(s0) << 32) | key2;
                    if (q0 > b0) b0 = q0;
                    float s1 = acc[mt][nj][2 + p] * s_binv[l];
                    unsigned long long q1 = ((unsigned long long)enc_f(s1) << 32) | key2;
                    if (q1 > b1) b1 = q1;
                }
            }
        }
        unsigned long long t;
        t = __shfl_xor_sync(0xffffffffu, b0, 1); if (t > b0) b0 = t;
        t = __shfl_xor_sync(0xffffffffu, b0, 2); if (t > b0) b0 = t;
        t = __shfl_xor_sync(0xffffffffu, b1, 1); if (t > b1) b1 = t;
        t = __shfl_xor_sync(0xffffffffu, b1, 2); if (t > b1) b1 = t;
        if ((lane & 3) == 0) {
            if (b0) atomicMax(&g_best[m0 + warp_m + mt * 16 + qr], b0);
            if (b1) atomicMax(&g_best[m0 + warp_m + mt * 16 + 8 + qr], b1);
        }
    }
}

// ---------------- finalize ----------------
__global__ __launch_bounds__(256) void finalize1_kernel(
    const float* __restrict__ bg2, const float* __restrict__ bp2,
    float* __restrict__ out_obs, float* __restrict__ out_meaning, int write_extra)
{
    __shared__ float sred[256];
    __shared__ float s_pm, s_inv, s_rinv;
    int t = blockIdx.x;
    int d = threadIdx.x;
    float v = g_obs_mean[(size_t)t * Dc + d];

    sred[d] = v * v;
    __syncthreads();
    for (int s = 128; s > 0; s >>= 1) {
        if (d < s) sred[d] += sred[d + s];
        __syncthreads();
    }
    if (d == 0) {
        float pm = 0.0f;
        float bg2v = bg2[0], bp2v = bp2[0];
        #pragma unroll
        for (int b = 0; b < Bc; b++) {
            int row = b * Tc + t;
            float gl = bg2v, pl = bp2v;
            #pragma unroll
            for (int jt = 0; jt < 4; jt++) gl += g_part[jt * MGP + row];
            #pragma unroll
            for (int jt = 4; jt < 8; jt++) pl += g_part[jt * MGP + row];
            pm += sigmoidf_(gl) * softplusf_(pl);
        }
        pm *= 0.25f;
        s_pm = pm;
        s_inv = 1.0f / fmaxf(sqrtf(sred[0]), EPSC);
    }
    __syncthreads();
    float ob = v * s_inv * s_pm;
    out_obs[(size_t)t * Dc + d] = ob;

    __syncthreads();
    sred[d] = ob * ob;
    __syncthreads();
    for (int s = 128; s > 0; s >>= 1) {
        if (d < s) sred[d] += sred[d + s];
        __syncthreads();
    }
    if (d == 0) {
        float rr = sqrtf(sred[0]);
        g_rad[t] = rr;
        s_rinv = 1.0f / fmaxf(rr, EPSC);
        if (write_extra) out_meaning[t] = (rr > 0.05f) ? 1.0f : 0.0f;
    }
    __syncthreads();
    // e4m3 o_angles scaled x16 (|angle| <= 1)
    uint16_t pk = pack_e4m3(ob * s_rinv * 16.0f, 0.0f);
    g_oang8[(size_t)t * Dc + d] = (unsigned char)(pk & 0xFF);
}

__global__ void init_best_kernel() {
    int i = blockIdx.x * blockDim.x + threadIdx.x;
    if (i < Tc) g_best[i] = 0ULL;
}

__global__ void finalize2_kernel(float* __restrict__ out_sims, float* __restrict__ out_slots) {
    int t = blockIdx.x * blockDim.x + threadIdx.x;
    if (t >= Tc) return;
    unsigned long long b = g_best[t];
    float sim = 0.0f;
    int idx = -1;
    bool has = (b != 0ULL);
    if (has) {
        sim = dec_f((unsigned)(b >> 32));
        idx = (int)(0xFFFFFFFFu - (unsigned)(b & 0xFFFFFFFFu));
    }
    bool matched = has && (g_rad[t] > 0.05f) && (sim > 0.5f);
    out_sims[t]  = matched ? sim : 0.0f;
    out_slots[t] = matched ? (float)idx : -1.0f;
}

// ---------------- launcher ----------------
extern "C" void kernel_launch(void* const* d_in, const int* in_sizes, int n_in,
                              void* d_out, int out_size)
{
    const float* hidden  = (const float*)d_in[0];
    const float* beliefs = (const float*)d_in[1];
    const void*  maskp   = d_in[2];
    const float* W_obs   = (const float*)d_in[3];
    const float* W_g1    = (const float*)d_in[4];
    const float* b_g1    = (const float*)d_in[5];
    const float* W_g2    = (const float*)d_in[6];
    const float* b_g2    = (const float*)d_in[7];
    const float* W_p1    = (const float*)d_in[8];
    const float* b_p1    = (const float*)d_in[9];
    const float* W_p2    = (const float*)d_in[10];
    const float* b_p2    = (const float*)d_in[11];
    float* out = (float*)d_out;

    static int attr_set = 0;
    if (!attr_set) {
        cudaFuncSetAttribute(gpobs_mma_kernel, cudaFuncAttributeMaxDynamicSharedMemorySize, DYN_SMEM);
        cudaFuncSetAttribute(sims_mma_kernel, cudaFuncAttributeMaxDynamicSharedMemorySize, 4 * SM_STG);
        attr_set = 1;
    }

    const size_t base = (size_t)Tc * Dc;
    const int write_extra = (out_size >= (int)(base + 3 * Tc)) ? 1 : 0;
    float* out_obs     = out;
    float* out_sims    = out + base;
    float* out_slots   = out + base + Tc;
    float* out_meaning = out + base + 2 * Tc;

    prep_hidden_kernel<<<(Tc * 512) / 256, 256>>>(hidden);
    prep_weights_kernel<<<(1280 * 512) / 256, 256>>>(W_g1, W_p1, W_obs);
    prep_small_kernel<<<4, 256>>>(b_g1, b_p1, W_g2, W_p2);
    prep_beliefs_kernel<<<((size_t)Nc * Dc / 4) / 256, 256>>>(beliefs);
    detect_mask_kernel<<<1, 256>>>((const unsigned char*)maskp, Nc);
    convert_mask_kernel<<<Nc / 256, 256>>>(maskp);
    binv_kernel<<<Nc / 8, 256>>>(beliefs);
    init_best_kernel<<<Tc / 256, 256>>>();

    gpobs_mma_kernel<<<dim3(9, MGP / 128), 256, DYN_SMEM>>>();
    finalize1_kernel<<<Tc, 256>>>(b_g2, b_p2, out_obs, out_meaning, write_extra);

    sims_mma_kernel<<<dim3(Nc / 128, Tc / 128), 256, 4 * SM_STG>>>();
    if (write_extra) {
        finalize2_kernel<<<Tc / 256, 256>>>(out_sims, out_slots);
    }
}

// round 8
// speedup vs baseline: 6.2592x; 1.1624x over previous
#include <cuda_runtime.h>
#include <cuda_fp16.h>
#include <cstdint>

#define Bc 4
#define Tc 4096
#define Hc 2048
#define Dc 256
#define Nc 32768
#define MGP (Bc*Tc)
#define EPSC 1e-8f
#define BLOB 8192            // one operand tile-chunk: 128 rows x 64B, SW64 swizzled

// ---------------- device scratch (tiled blob layouts) ----------------
__device__ unsigned char g_Af[(size_t)128 * 64 * BLOB];    // hidden fp16: 128 m-tiles x 64 chunks
__device__ unsigned char g_Hmhi[(size_t)32 * 64 * BLOB];   // mean hidden hi
__device__ unsigned char g_Hmlo[(size_t)32 * 64 * BLOB];   // mean hidden lo
__device__ unsigned char g_Wcf[(size_t)8 * 64 * BLOB];     // gate+prec W1 fp16: 8 n-tiles
__device__ unsigned char g_Wohi[(size_t)2 * 64 * BLOB];    // W_obs hi: 2 n-tiles
__device__ unsigned char g_Wolo[(size_t)2 * 64 * BLOB];
__device__ unsigned char g_Bb8[(size_t)256 * 4 * BLOB];    // beliefs e4m3 x16
__device__ unsigned char g_oang8[(size_t)32 * 4 * BLOB];   // o_angles e4m3 x16
__device__ float g_bc1[1024];
__device__ float g_wc2[1024];
__device__ float g_obs_mean[(size_t)Tc * Dc];
__device__ float g_part[8 * MGP];
__device__ float g_binv[Nc];                               // 1/(256*clip(norm,eps))
__device__ unsigned char g_active[Nc];
__device__ unsigned long long g_best[Tc];
__device__ float g_rad[Tc];
__device__ int g_fmt;

// ---------------- helpers ----------------
__device__ __forceinline__ uint32_t smem_u32(const void* p) {
    uint32_t a;
    asm("{ .reg .u64 t; cvta.to.shared.u64 t, %1; cvt.u32.u64 %0, t; }" : "=r"(a) : "l"(p));
    return a;
}
#define LDSM4(R0, R1, R2, R3, A) \
    asm volatile("ldmatrix.sync.aligned.m8n8.x4.shared.b16 {%0,%1,%2,%3}, [%4];" \
        : "=r"(R0), "=r"(R1), "=r"(R2), "=r"(R3) : "r"(A))
#define MMA_F16(D, A, B) \
    asm volatile("mma.sync.aligned.m16n8k16.row.col.f32.f16.f16.f32 " \
        "{%0,%1,%2,%3}, {%4,%5,%6,%7}, {%8,%9}, {%0,%1,%2,%3};" \
        : "+f"((D)[0]), "+f"((D)[1]), "+f"((D)[2]), "+f"((D)[3]) \
        : "r"((A)[0]), "r"((A)[1]), "r"((A)[2]), "r"((A)[3]), "r"((B)[0]), "r"((B)[1]))
#define MMA_F8(D, A, B) \
    asm volatile("mma.sync.aligned.m16n8k32.row.col.f32.e4m3.e4m3.f32 " \
        "{%0,%1,%2,%3}, {%4,%5,%6,%7}, {%8,%9}, {%0,%1,%2,%3};" \
        : "+f"((D)[0]), "+f"((D)[1]), "+f"((D)[2]), "+f"((D)[3]) \
        : "r"((A)[0]), "r"((A)[1]), "r"((A)[2]), "r"((A)[3]), "r"((B)[0]), "r"((B)[1]))
#define CPBULK(DST, SRC, BYTES, MBAR) \
    asm volatile("cp.async.bulk.shared::cta.global.mbarrier::complete_tx::bytes [%0], [%1], %2, [%3];" \
        :: "r"((uint32_t)(DST)), "l"(SRC), "r"((uint32_t)(BYTES)), "r"((uint32_t)(MBAR)) : "memory")
#define MBAR_INIT(mb, n) \
    asm volatile("mbarrier.init.shared.b64 [%0], %1;" :: "r"((uint32_t)(mb)), "r"((uint32_t)(n)) : "memory")
#define MBAR_EXPECT_TX(mb, bytes) \
    asm volatile("mbarrier.arrive.expect_tx.shared.b64 _, [%0], %1;" \
        :: "r"((uint32_t)(mb)), "r"((uint32_t)(bytes)) : "memory")
#define MBAR_WAIT(mb, ph) do { \
    uint32_t _m = (uint32_t)(mb); uint32_t _p = (uint32_t)(ph); uint32_t _d; \
    asm volatile("{\n\t.reg .pred p;\n\t" \
        "mbarrier.try_wait.parity.acquire.cta.shared::cta.b64 p, [%1], %2;\n\t" \
        "selp.b32 %0, 1, 0, p;\n\t}" : "=r"(_d) : "r"(_m), "r"(_p) : "memory"); \
    if (!_d) { \
        asm volatile("{\n\t.reg .pred P1;\n\t" \
            "WL_%=:\n\t" \
            "mbarrier.try_wait.parity.acquire.cta.shared::cta.b64 P1, [%0], %1, 0x989680;\n\t" \
            "@P1 bra.uni WD_%=;\n\t" \
            "bra.uni WL_%=;\n\t" \
            "WD_%=:\n\t}" :: "r"(_m), "r"(_p) : "memory"); \
    } } while (0)

__device__ __forceinline__ unsigned enc_f(float f) {
    unsigned u = __float_as_uint(f);
    return (u & 0x80000000u) ? ~u : (u | 0x80000000u);
}
__device__ __forceinline__ float dec_f(unsigned e) {
    unsigned u = (e & 0x80000000u) ? (e ^ 0x80000000u) : ~e;
    return __uint_as_float(u);
}
__device__ __forceinline__ float sigmoidf_(float x) { return 1.0f / (1.0f + expf(-x)); }
__device__ __forceinline__ float softplusf_(float x) {
    return fmaxf(x, 0.0f) + log1pf(expf(-fabsf(x)));
}
__device__ __forceinline__ uint16_t pack_e4m3(float lo, float hi) {
    uint16_t r;
    asm("cvt.rn.satfinite.e4m3x2.f32 %0, %1, %2;" : "=h"(r) : "f"(hi), "f"(lo));
    return r;
}
__device__ __forceinline__ uint32_t pk_h2(float a, float b) {
    __half2 h = __halves2half2(__float2half_rn(a), __float2half_rn(b));
    return *(uint32_t*)&h;
}

// ---------------- prep kernels (write tiled swizzled blobs) ----------------
__global__ void prep_hidden_kernel(const float* __restrict__ hidden) {
    int idx = blockIdx.x * blockDim.x + threadIdx.x;   // Tc*64
    int t = idx >> 6, c = idx & 63;
    const int r = t & 127;
    const int sw = (r >> 1) & 3;
    float acc[32];
    #pragma unroll
    for (int j = 0; j < 32; j++) acc[j] = 0.0f;
    #pragma unroll
    for (int b = 0; b < Bc; b++) {
        const float* src = hidden + ((size_t)(b * Tc + t)) * Hc + c * 32;
        float v[32];
        #pragma unroll
        for (int q = 0; q < 8; q++) {
            float4 f = *(const float4*)(src + q * 4);
            v[q*4+0] = f.x; v[q*4+1] = f.y; v[q*4+2] = f.z; v[q*4+3] = f.w;
        }
        #pragma unroll
        for (int j = 0; j < 32; j++) acc[j] += v[j];
        char* dst = (char*)g_Af + ((size_t)(((b * Tc + t) >> 7) * 64 + c)) * BLOB + r * 64;
        #pragma unroll
        for (int k16 = 0; k16 < 4; k16++) {
            uint4 u = make_uint4(pk_h2(v[k16*8+0], v[k16*8+1]), pk_h2(v[k16*8+2], v[k16*8+3]),
                                 pk_h2(v[k16*8+4], v[k16*8+5]), pk_h2(v[k16*8+6], v[k16*8+7]));
            *(uint4*)(dst + ((k16 ^ sw) << 4)) = u;
        }
    }
    float hi[32], lo[32];
    #pragma unroll
    for (int j = 0; j < 32; j++) {
        float m = acc[j] * 0.25f;
        float h = __half2float(__float2half_rn(m));
        hi[j] = m;
        lo[j] = m - h;
    }
    size_t boff = ((size_t)((t >> 7) * 64 + c)) * BLOB + r * 64;
    char* dh = (char*)g_Hmhi + boff;
    char* dl = (char*)g_Hmlo + boff;
    #pragma unroll
    for (int k16 = 0; k16 < 4; k16++) {
        uint4 uh = make_uint4(pk_h2(hi[k16*8+0], hi[k16*8+1]), pk_h2(hi[k16*8+2], hi[k16*8+3]),
                              pk_h2(hi[k16*8+4], hi[k16*8+5]), pk_h2(hi[k16*8+6], hi[k16*8+7]));
        uint4 ul = make_uint4(pk_h2(lo[k16*8+0], lo[k16*8+1]), pk_h2(lo[k16*8+2], lo[k16*8+3]),
                              pk_h2(lo[k16*8+4], lo[k16*8+5]), pk_h2(lo[k16*8+6], lo[k16*8+7]));
        *(uint4*)(dh + ((k16 ^ sw) << 4)) = uh;
        *(uint4*)(dl + ((k16 ^ sw) << 4)) = ul;
    }
}

__global__ void prep_weights_kernel(const float* __restrict__ Wg1, const float* __restrict__ Wp1,
                                    const float* __restrict__ Wobs) {
    int idx = blockIdx.x * blockDim.x + threadIdx.x;   // 1280*64
    int row = idx >> 6, c = idx & 63;
    float v[32];
    const float* src;
    if (row < 512)        src = Wg1 + (size_t)row * Hc + c * 32;
    else if (row < 1024)  src = Wp1 + (size_t)(row - 512) * Hc + c * 32;
    else                  src = Wobs + (size_t)(row - 1024) * Hc + c * 32;
    #pragma unroll
    for (int q = 0; q < 8; q++) {
        float4 f = *(const float4*)(src + q * 4);
        v[q*4+0] = f.x; v[q*4+1] = f.y; v[q*4+2] = f.z; v[q*4+3] = f.w;
    }
    if (row < 1024) {
        int r = row & 127, sw = (r >> 1) & 3;
        char* dst = (char*)g_Wcf + ((size_t)((row >> 7) * 64 + c)) * BLOB + r * 64;
        #pragma unroll
        for (int k16 = 0; k16 < 4; k16++) {
            uint4 u = make_uint4(pk_h2(v[k16*8+0], v[k16*8+1]), pk_h2(v[k16*8+2], v[k16*8+3]),
                                 pk_h2(v[k16*8+4], v[k16*8+5]), pk_h2(v[k16*8+6], v[k16*8+7]));
            *(uint4*)(dst + ((k16 ^ sw) << 4)) = u;
        }
    } else {
        int r2 = row - 1024;
        int r = r2 & 127, sw = (r >> 1) & 3;
        size_t boff = ((size_t)((r2 >> 7) * 64 + c)) * BLOB + r * 64;
        char* dh = (char*)g_Wohi + boff;
        char* dl = (char*)g_Wolo + boff;
        float hi[32], lo[32];
        #pragma unroll
        for (int j = 0; j < 32; j++) {
            float h = __half2float(__float2half_rn(v[j]));
            hi[j] = v[j];
            lo[j] = v[j] - h;
        }
        #pragma unroll
        for (int k16 = 0; k16 < 4; k16++) {
            uint4 uh = make_uint4(pk_h2(hi[k16*8+0], hi[k16*8+1]), pk_h2(hi[k16*8+2], hi[k16*8+3]),
                                  pk_h2(hi[k16*8+4], hi[k16*8+5]), pk_h2(hi[k16*8+6], hi[k16*8+7]));
            uint4 ul = make_uint4(pk_h2(lo[k16*8+0], lo[k16*8+1]), pk_h2(lo[k16*8+2], lo[k16*8+3]),
                                  pk_h2(lo[k16*8+4], lo[k16*8+5]), pk_h2(lo[k16*8+6], lo[k16*8+7]));
            *(uint4*)(dh + ((k16 ^ sw) << 4)) = uh;
            *(uint4*)(dl + ((k16 ^ sw) << 4)) = ul;
        }
    }
}

__global__ void prep_small_kernel(const float* __restrict__ bg1, const float* __restrict__ bp1,
                                  const float* __restrict__ Wg2, const float* __restrict__ Wp2) {
    int i = blockIdx.x * blockDim.x + threadIdx.x;
    if (i < 1024) {
        g_bc1[i] = (i < 512) ? bg1[i] : bp1[i - 512];
        g_wc2[i] = (i < 512) ? Wg2[i] : Wp2[i - 512];
    }
}

__global__ void prep_beliefs_kernel(const float* __restrict__ beliefs) {
    int idx = blockIdx.x * blockDim.x + threadIdx.x;   // Nc*4
    int n = idx >> 2, c = idx & 3;
    int r = n & 127, sw = (r >> 1) & 3;
    const float* src = beliefs + (size_t)n * Dc + c * 64;
    char* dst = (char*)g_Bb8 + ((size_t)((n >> 7) * 4 + c)) * BLOB + r * 64;
    #pragma unroll
    for (int k16 = 0; k16 < 4; k16++) {
        uint32_t w[4];
        #pragma unroll
        for (int q = 0; q < 4; q++) {
            float4 f = *(const float4*)(src + k16 * 16 + q * 4);
            uint16_t a = pack_e4m3(f.x * 16.0f, f.y * 16.0f);
            uint16_t b = pack_e4m3(f.z * 16.0f, f.w * 16.0f);
            w[q] = ((uint32_t)b << 16) | a;
        }
        *(uint4*)(dst + ((k16 ^ sw) << 4)) = make_uint4(w[0], w[1], w[2], w[3]);
    }
}

__global__ void detect_mask_kernel(const unsigned char* __restrict__ m, int nbytes) {
    __shared__ int weird, off4;
    if (threadIdx.x == 0) { weird = 0; off4 = 0; }
    __syncthreads();
    for (int i = threadIdx.x; i < nbytes; i += blockDim.x) {
        unsigned char c = m[i];
        if (c > 1) atomicOr(&weird, 1);
        if (c != 0 && (i & 3)) atomicOr(&off4, 1);
    }
    __syncthreads();
    if (threadIdx.x == 0) g_fmt = weird ? 2 : (off4 ? 1 : 0);
}
__global__ void convert_mask_kernel(const void* __restrict__ m) {
    int i = blockIdx.x * blockDim.x + threadIdx.x;
    if (i >= Nc) return;
    int fmt = g_fmt;
    unsigned char a;
    if (fmt == 0)      a = (((const int*)m)[i] != 0);
    else if (fmt == 1) a = (((const unsigned char*)m)[i] != 0);
    else               a = (((const float*)m)[i] != 0.0f);
    g_active[i] = a;
}
__global__ void binv_kernel(const float* __restrict__ beliefs) {
    int row = blockIdx.x * 8 + (threadIdx.x >> 5);
    int lane = threadIdx.x & 31;
    const float4* p = reinterpret_cast<const float4*>(beliefs + (size_t)row * Dc);
    float s = 0.0f;
    #pragma unroll
    for (int r = 0; r < 2; r++) {
        float4 v = p[lane + r * 32];
        s += v.x * v.x + v.y * v.y + v.z * v.z + v.w * v.w;
    }
    #pragma unroll
    for (int o = 16; o > 0; o >>= 1) s += __shfl_down_sync(0xffffffffu, s, o);
    if (lane == 0) g_binv[row] = 1.0f / (256.0f * fmaxf(sqrtf(s), EPSC));
}

// ============ merged gate/prec + obs GEMM kernel (bulk-copy pipelines) ============
#define GP_STAGE 16384
#define OB_STAGE 32768
#define DYN_SMEM 65536

__global__ __launch_bounds__(256, 2) void gpobs_mma_kernel() {
    extern __shared__ __align__(128) char dsm[];
    __shared__ float s_b1[128], s_w2[128], s_red[128];
    __shared__ __align__(8) unsigned long long s_mbar[4];

    const int tid = threadIdx.x, lane = tid & 31, wid = tid >> 5;
    const int warp_m = (wid >> 1) * 32;
    const int warp_n = (wid & 1) * 64;
    const uint32_t sbase = smem_u32(dsm);
    const uint32_t mb = smem_u32(s_mbar);

    const int rowA = warp_m + (lane & 15);
    const uint32_t cA = (uint32_t)(lane >> 4);
    const uint32_t swA = (uint32_t)((rowA >> 1) & 3);
    const uint32_t aoff = (uint32_t)rowA * 64;
    const int rowB = warp_n + ((lane >> 4) << 3) + (lane & 7);
    const uint32_t cB = (uint32_t)((lane >> 3) & 1);
    const uint32_t swB = (uint32_t)((rowB >> 1) & 3);
    const uint32_t boff = (uint32_t)rowB * 64;

    float acc[2][8][4];
    #pragma unroll
    for (int i = 0; i < 2; i++)
        #pragma unroll
        for (int j = 0; j < 8; j++)
            #pragma unroll
            for (int k = 0; k < 4; k++) acc[i][j][k] = 0.0f;

    const int qr = lane >> 2;
    const int qc = (lane & 3) * 2;

    if (blockIdx.x < 8) {
        // ---------------- gate/prec path: fp16 single-term, 4-stage ----------------
        const int nt = blockIdx.x;
        const int mt = blockIdx.y;
        const int m0 = mt * 128, nbase = nt * 128;
        if (tid < 128) {
            s_b1[tid] = g_bc1[nbase + tid];
            s_w2[tid] = g_wc2[nbase + tid];
            s_red[tid] = 0.0f;
        }
        const char* gA = (const char*)g_Af + (size_t)mt * 64 * BLOB;
        const char* gB = (const char*)g_Wcf + (size_t)nt * 64 * BLOB;

        if (tid == 0) {
            #pragma unroll
            for (int s = 0; s < 4; s++) MBAR_INIT(mb + s * 8, 1);
        }
        __syncthreads();
        if (tid == 0) {
            #pragma unroll
            for (int c = 0; c < 3; c++) {
                MBAR_EXPECT_TX(mb + c * 8, GP_STAGE);
                CPBULK(sbase + c * GP_STAGE,        gA + (size_t)c * BLOB, BLOB, mb + c * 8);
                CPBULK(sbase + c * GP_STAGE + BLOB, gB + (size_t)c * BLOB, BLOB, mb + c * 8);
            }
        }

        for (int c = 0; c < 64; c++) {
            MBAR_WAIT(mb + (c & 3) * 8, (c >> 2) & 1);
            __syncthreads();
            if (tid == 0 && c + 3 < 64) {
                const int s = (c + 3) & 3;
                MBAR_EXPECT_TX(mb + s * 8, GP_STAGE);
                CPBULK(sbase + s * GP_STAGE,        gA + (size_t)(c + 3) * BLOB, BLOB, mb + s * 8);
                CPBULK(sbase + s * GP_STAGE + BLOB, gB + (size_t)(c + 3) * BLOB, BLOB, mb + s * 8);
            }
            const uint32_t uA = sbase + (c & 3) * GP_STAGE;
            const uint32_t uB = uA + BLOB;
            #pragma unroll
            for (int ks = 0; ks < 2; ks++) {
                const uint32_t oa = ((cA | (ks << 1)) ^ swA) << 4;
                const uint32_t ob = ((cB | (ks << 1)) ^ swB) << 4;
                uint32_t a[2][4];
                LDSM4(a[0][0], a[0][1], a[0][2], a[0][3], uA + aoff + oa);
                LDSM4(a[1][0], a[1][1], a[1][2], a[1][3], uA + aoff + 1024 + oa);
                uint32_t b[8][2];
                #pragma unroll
                for (int jp = 0; jp < 4; jp++) {
                    LDSM4(b[2*jp][0], b[2*jp][1], b[2*jp+1][0], b[2*jp+1][1],
                          uB + boff + (uint32_t)jp * 1024 + ob);
                }
                #pragma unroll
                for (int mt2 = 0; mt2 < 2; mt2++)
                    #pragma unroll
                    for (int nj = 0; nj < 8; nj++)
                        MMA_F16(acc[mt2][nj], a[mt2], b[nj]);
            }
        }
        __syncthreads();

        #pragma unroll
        for (int mt2 = 0; mt2 < 2; mt2++) {
            float p0 = 0.0f, p1 = 0.0f;
            #pragma unroll
            for (int nj = 0; nj < 8; nj++) {
                int col = warp_n + nj * 8 + qc;
                p0 += fmaxf(acc[mt2][nj][0] + s_b1[col], 0.0f) * s_w2[col]
                    + fmaxf(acc[mt2][nj][1] + s_b1[col + 1], 0.0f) * s_w2[col + 1];
                p1 += fmaxf(acc[mt2][nj][2] + s_b1[col], 0.0f) * s_w2[col]
                    + fmaxf(acc[mt2][nj][3] + s_b1[col + 1], 0.0f) * s_w2[col + 1];
            }
            p0 += __shfl_xor_sync(0xffffffffu, p0, 1);
            p0 += __shfl_xor_sync(0xffffffffu, p0, 2);
            p1 += __shfl_xor_sync(0xffffffffu, p1, 1);
            p1 += __shfl_xor_sync(0xffffffffu, p1, 2);
            if ((lane & 3) == 0) {
                atomicAdd(&s_red[warp_m + mt2 * 16 + qr], p0);
                atomicAdd(&s_red[warp_m + mt2 * 16 + 8 + qr], p1);
            }
        }
        __syncthreads();
        if (tid < 128) g_part[nt * MGP + m0 + tid] = s_red[tid];
    } else {
        // ---------------- obs path: fp16 3-term hi/lo, 2-stage ----------------
        const int id = blockIdx.y;
        if (id >= 64) return;
        const int nt = id & 1;
        const int mt = id >> 1;
        const int m0 = mt * 128, nbase = nt * 128;
        const char* gAh = (const char*)g_Hmhi + (size_t)mt * 64 * BLOB;
        const char* gAl = (const char*)g_Hmlo + (size_t)mt * 64 * BLOB;
        const char* gBh = (const char*)g_Wohi + (size_t)nt * 64 * BLOB;
        const char* gBl = (const char*)g_Wolo + (size_t)nt * 64 * BLOB;

        if (tid == 0) {
            MBAR_INIT(mb, 1);
            MBAR_INIT(mb + 8, 1);
        }
        __syncthreads();
        if (tid == 0) {
            MBAR_EXPECT_TX(mb, OB_STAGE);
            CPBULK(sbase,         gAh, BLOB, mb);
            CPBULK(sbase + 8192,  gAl, BLOB, mb);
            CPBULK(sbase + 16384, gBh, BLOB, mb);
            CPBULK(sbase + 24576, gBl, BLOB, mb);
        }

        for (int c = 0; c < 64; c++) {
            MBAR_WAIT(mb + (c & 1) * 8, (c >> 1) & 1);
            __syncthreads();
            if (tid == 0 && c + 1 < 64) {
                const int s = (c + 1) & 1;
                const uint32_t st = sbase + s * OB_STAGE;
                MBAR_EXPECT_TX(mb + s * 8, OB_STAGE);
                CPBULK(st,         gAh + (size_t)(c + 1) * BLOB, BLOB, mb + s * 8);
                CPBULK(st + 8192,  gAl + (size_t)(c + 1) * BLOB, BLOB, mb + s * 8);
                CPBULK(st + 16384, gBh + (size_t)(c + 1) * BLOB, BLOB, mb + s * 8);
                CPBULK(st + 24576, gBl + (size_t)(c + 1) * BLOB, BLOB, mb + s * 8);
            }
            const uint32_t uS = sbase + (c & 1) * OB_STAGE;
            #pragma unroll
            for (int tr = 0; tr < 3; tr++) {
                const uint32_t uA = uS + (tr == 2 ? 8192u : 0u);
                const uint32_t uB = uS + 16384u + (tr == 1 ? 8192u : 0u);
                #pragma unroll
                for (int ks = 0; ks < 2; ks++) {
                    const uint32_t oa = ((cA | (ks << 1)) ^ swA) << 4;
                    const uint32_t ob = ((cB | (ks << 1)) ^ swB) << 4;
                    uint32_t a[2][4];
                    LDSM4(a[0][0], a[0][1], a[0][2], a[0][3], uA + aoff + oa);
                    LDSM4(a[1][0], a[1][1], a[1][2], a[1][3], uA + aoff + 1024 + oa);
                    uint32_t b[8][2];
                    #pragma unroll
                    for (int jp = 0; jp < 4; jp++) {
                        LDSM4(b[2*jp][0], b[2*jp][1], b[2*jp+1][0], b[2*jp+1][1],
                              uB + boff + (uint32_t)jp * 1024 + ob);
                    }
                    #pragma unroll
                    for (int mt2 = 0; mt2 < 2; mt2++)
                        #pragma unroll
                        for (int nj = 0; nj < 8; nj++)
                            MMA_F16(acc[mt2][nj], a[mt2], b[nj]);
                }
            }
        }

        #pragma unroll
        for (int mt2 = 0; mt2 < 2; mt2++)
            #pragma unroll
            for (int nj = 0; nj < 8; nj++) {
                int row = m0 + warp_m + mt2 * 16 + qr;
                int col = nbase + warp_n + nj * 8 + qc;
                *(float2*)(g_obs_mean + (size_t)row * Dc + col) = make_float2(acc[mt2][nj][0], acc[mt2][nj][1]);
                *(float2*)(g_obs_mean + (size_t)(row + 8) * Dc + col) = make_float2(acc[mt2][nj][2], acc[mt2][nj][3]);
            }
    }
}

// ============ sims GEMM: fp8 e4m3, bulk-copy 4-stage + masked argmax ============
__global__ __launch_bounds__(256, 2) void sims_mma_kernel() {
    extern __shared__ __align__(128) char dsm[];
    __shared__ float s_binv[128];
    __shared__ unsigned char s_act[128];
    __shared__ __align__(8) unsigned long long s_mbar[4];

    const int tid = threadIdx.x, lane = tid & 31, wid = tid >> 5;
    const int nt = blockIdx.x;
    const int mt = blockIdx.y;
    const int n0 = nt * 128, m0 = mt * 128;
    const int warp_m = (wid >> 1) * 32;
    const int warp_n = (wid & 1) * 64;
    const uint32_t sbase = smem_u32(dsm);
    const uint32_t mb = smem_u32(s_mbar);

    if (tid < 128) { s_binv[tid] = g_binv[n0 + tid]; s_act[tid] = g_active[n0 + tid]; }

    const int rowA = warp_m + (lane & 15);
    const uint32_t cA = (uint32_t)(lane >> 4);
    const uint32_t swA = (uint32_t)((rowA >> 1) & 3);
    const uint32_t aoff = (uint32_t)rowA * 64;
    const int rowB = warp_n + ((lane >> 4) << 3) + (lane & 7);
    const uint32_t cB = (uint32_t)((lane >> 3) & 1);
    const uint32_t swB = (uint32_t)((rowB >> 1) & 3);
    const uint32_t boff = (uint32_t)rowB * 64;

    const char* gA = (const char*)g_oang8 + (size_t)mt * 4 * BLOB;
    const char* gB = (const char*)g_Bb8 + (size_t)nt * 4 * BLOB;

    float acc[2][8][4];
    #pragma unroll
    for (int i = 0; i < 2; i++)
        #pragma unroll
        for (int j = 0; j < 8; j++)
            #pragma unroll
            for (int k = 0; k < 4; k++) acc[i][j][k] = 0.0f;

    if (tid == 0) {
        #pragma unroll
        for (int s = 0; s < 4; s++) MBAR_INIT(mb + s * 8, 1);
    }
    __syncthreads();
    if (tid == 0) {
        #pragma unroll
        for (int c = 0; c < 3; c++) {
            MBAR_EXPECT_TX(mb + c * 8, GP_STAGE);
            CPBULK(sbase + c * GP_STAGE,        gA + (size_t)c * BLOB, BLOB, mb + c * 8);
            CPBULK(sbase + c * GP_STAGE + BLOB, gB + (size_t)c * BLOB, BLOB, mb + c * 8);
        }
    }

    for (int c = 0; c < 4; c++) {
        MBAR_WAIT(mb + (c & 3) * 8, 0);
        __syncthreads();
        if (tid == 0 && c + 3 < 4) {
            const int s = (c + 3) & 3;
            MBAR_EXPECT_TX(mb + s * 8, GP_STAGE);
            CPBULK(sbase + s * GP_STAGE,        gA + (size_t)(c + 3) * BLOB, BLOB, mb + s * 8);
            CPBULK(sbase + s * GP_STAGE + BLOB, gB + (size_t)(c + 3) * BLOB, BLOB, mb + s * 8);
        }
        const uint32_t uA = sbase + (c & 3) * GP_STAGE;
        const uint32_t uB = uA + BLOB;
        #pragma unroll
        for (int ks = 0; ks < 2; ks++) {
            const uint32_t oa = ((cA | (ks << 1)) ^ swA) << 4;
            const uint32_t ob = ((cB | (ks << 1)) ^ swB) << 4;
            uint32_t a[2][4];
            LDSM4(a[0][0], a[0][1], a[0][2], a[0][3], uA + aoff + oa);
            LDSM4(a[1][0], a[1][1], a[1][2], a[1][3], uA + aoff + 1024 + oa);
            uint32_t b[8][2];
            #pragma unroll
            for (int jp = 0; jp < 4; jp++) {
                LDSM4(b[2*jp][0], b[2*jp][1], b[2*jp+1][0], b[2*jp+1][1],
                      uB + boff + (uint32_t)jp * 1024 + ob);
            }
            #pragma unroll
            for (int mt2 = 0; mt2 < 2; mt2++)
                #pragma unroll
                for (int nj = 0; nj < 8; nj++)
                    MMA_F8(acc[mt2][nj], a[mt2], b[nj]);
        }
    }

    const int qr = lane >> 2;
    const int qc = (lane & 3) * 2;
    #pragma unroll
    for (int mt2 = 0; mt2 < 2; mt2++) {
        unsigned long long b0 = 0ULL, b1 = 0ULL;
        #pragma unroll
        for (int nj = 0; nj < 8; nj++) {
            int ln = warp_n + nj * 8 + qc;
            #pragma unroll
            for (int p = 0; p < 2; p++) {
                int l = ln + p;
                if (s_act[l]) {
                    unsigned long long key2 = 0xFFFFFFFFu - (unsigned)(n0 + l);
                    float s0 = acc[mt2][nj][p] * s_binv[l];
                    unsigned long long q0 = ((unsigned long long)enc_f(s0) << 32) | key2;
                    if (q0 > b0) b0 = q0;
                    float s1 = acc[mt2][nj][2 + p] * s_binv[l];
                    unsigned long long q1 = ((unsigned long long)enc_f(s1) << 32) | key2;
                    if (q1 > b1) b1 = q1;
                }
            }
        }
        unsigned long long t;
        t = __shfl_xor_sync(0xffffffffu, b0, 1); if (t > b0) b0 = t;
        t = __shfl_xor_sync(0xffffffffu, b0, 2); if (t > b0) b0 = t;
        t = __shfl_xor_sync(0xffffffffu, b1, 1); if (t > b1) b1 = t;
        t = __shfl_xor_sync(0xffffffffu, b1, 2); if (t > b1) b1 = t;
        if ((lane & 3) == 0) {
            if (b0) atomicMax(&g_best[m0 + warp_m + mt2 * 16 + qr], b0);
            if (b1) atomicMax(&g_best[m0 + warp_m + mt2 * 16 + 8 + qr], b1);
        }
    }
}

// ---------------- finalize ----------------
__global__ __launch_bounds__(256) void finalize1_kernel(
    const float* __restrict__ bg2, const float* __restrict__ bp2,
    float* __restrict__ out_obs, float* __restrict__ out_meaning, int write_extra)
{
    __shared__ float sred[256];
    __shared__ float s_pm, s_inv, s_rinv;
    int t = blockIdx.x;
    int d = threadIdx.x;
    float v = g_obs_mean[(size_t)t * Dc + d];

    sred[d] = v * v;
    __syncthreads();
    for (int s = 128; s > 0; s >>= 1) {
        if (d < s) sred[d] += sred[d + s];
        __syncthreads();
    }
    if (d == 0) {
        float pm = 0.0f;
        float bg2v = bg2[0], bp2v = bp2[0];
        #pragma unroll
        for (int b = 0; b < Bc; b++) {
            int row = b * Tc + t;
            float gl = bg2v, pl = bp2v;
            #pragma unroll
            for (int jt = 0; jt < 4; jt++) gl += g_part[jt * MGP + row];
            #pragma unroll
            for (int jt = 4; jt < 8; jt++) pl += g_part[jt * MGP + row];
            pm += sigmoidf_(gl) * softplusf_(pl);
        }
        pm *= 0.25f;
        s_pm = pm;
        s_inv = 1.0f / fmaxf(sqrtf(sred[0]), EPSC);
    }
    __syncthreads();
    float ob = v * s_inv * s_pm;
    out_obs[(size_t)t * Dc + d] = ob;

    __syncthreads();
    sred[d] = ob * ob;
    __syncthreads();
    for (int s = 128; s > 0; s >>= 1) {
        if (d < s) sred[d] += sred[d + s];
        __syncthreads();
    }
    if (d == 0) {
        float rr = sqrtf(sred[0]);
        g_rad[t] = rr;
        s_rinv = 1.0f / fmaxf(rr, EPSC);
        if (write_extra) out_meaning[t] = (rr > 0.05f) ? 1.0f : 0.0f;
    }
    __syncthreads();
    {
        uint16_t pk = pack_e4m3(ob * s_rinv * 16.0f, 0.0f);
        int mt = t >> 7, r = t & 127, sw = (r >> 1) & 3;
        int c = d >> 6;
        int pos = d & 63;
        int k16 = pos >> 4;
        size_t off = ((size_t)(mt * 4 + c)) * BLOB + r * 64 + ((k16 ^ sw) << 4) + (pos & 15);
        g_oang8[off] = (unsigned char)(pk & 0xFF);
    }
}

__global__ void init_best_kernel() {
    int i = blockIdx.x * blockDim.x + threadIdx.x;
    if (i < Tc) g_best[i] = 0ULL;
}

__global__ void finalize2_kernel(float* __restrict__ out_sims, float* __restrict__ out_slots) {
    int t = blockIdx.x * blockDim.x + threadIdx.x;
    if (t >= Tc) return;
    unsigned long long b = g_best[t];
    float sim = 0.0f;
    int idx = -1;
    bool has = (b != 0ULL);
    if (has) {
        sim = dec_f((unsigned)(b >> 32));
        idx = (int)(0xFFFFFFFFu - (unsigned)(b & 0xFFFFFFFFu));
    }
    bool matched = has && (g_rad[t] > 0.05f) && (sim > 0.5f);
    out_sims[t]  = matched ? sim : 0.0f;
    out_slots[t] = matched ? (float)idx : -1.0f;
}

// ---------------- launcher ----------------
extern "C" void kernel_launch(void* const* d_in, const int* in_sizes, int n_in,
                              void* d_out, int out_size)
{
    const float* hidden  = (const float*)d_in[0];
    const float* beliefs = (const float*)d_in[1];
    const void*  maskp   = d_in[2];
    const float* W_obs   = (const float*)d_in[3];
    const float* W_g1    = (const float*)d_in[4];
    const float* b_g1    = (const float*)d_in[5];
    const float* W_g2    = (const float*)d_in[6];
    const float* b_g2    = (const float*)d_in[7];
    const float* W_p1    = (const float*)d_in[8];
    const float* b_p1    = (const float*)d_in[9];
    const float* W_p2    = (const float*)d_in[10];
    const float* b_p2    = (const float*)d_in[11];
    float* out = (float*)d_out;

    static int attr_set = 0;
    if (!attr_set) {
        cudaFuncSetAttribute(gpobs_mma_kernel, cudaFuncAttributeMaxDynamicSharedMemorySize, DYN_SMEM);
        cudaFuncSetAttribute(sims_mma_kernel, cudaFuncAttributeMaxDynamicSharedMemorySize, DYN_SMEM);
        attr_set = 1;
    }

    const size_t base = (size_t)Tc * Dc;
    const int write_extra = (out_size >= (int)(base + 3 * Tc)) ? 1 : 0;
    float* out_obs     = out;
    float* out_sims    = out + base;
    float* out_slots   = out + base + Tc;
    float* out_meaning = out + base + 2 * Tc;

    prep_hidden_kernel<<<(Tc * 64) / 256, 256>>>(hidden);
    prep_weights_kernel<<<(1280 * 64) / 256, 256>>>(W_g1, W_p1, W_obs);
    prep_small_kernel<<<4, 256>>>(b_g1, b_p1, W_g2, W_p2);
    gpobs_mma_kernel<<<dim3(9, MGP / 128), 256, DYN_SMEM>>>();   // my-index 3: profiled launch
    prep_beliefs_kernel<<<(Nc * 4) / 256, 256>>>(beliefs);
    detect_mask_kernel<<<1, 256>>>((const unsigned char*)maskp, Nc);
    convert_mask_kernel<<<Nc / 256, 256>>>(maskp);
    binv_kernel<<<Nc / 8, 256>>>(beliefs);
    init_best_kernel<<<Tc / 256, 256>>>();
    finalize1_kernel<<<Tc, 256>>>(b_g2, b_p2, out_obs, out_meaning, write_extra);
    sims_mma_kernel<<<dim3(Nc / 128, Tc / 128), 256, DYN_SMEM>>>();
    if (write_extra) {
        finalize2_kernel<<<Tc / 256, 256>>>(out_sims, out_slots);
    }
}